// round 10
// baseline (speedup 1.0000x reference)
#include <cuda_runtime.h>
#include <cuda_bf16.h>
#include <math.h>
#include <stdint.h>

#define BB     2
#define TT     2048
#define TE     2052
#define DIMM   1024
#define DD     64
#define NATTN  8
#define NKV    4
#define NSSM   8
#define SS     16
#define NMETA  4

// ================= helpers =================
__device__ __forceinline__ uint32_t smem_u32(const void* p) {
    uint32_t a;
    asm("{ .reg .u64 t; cvta.to.shared.u64 t, %1; cvt.u32.u64 %0, t; }" : "=r"(a) : "l"(p));
    return a;
}
__device__ __forceinline__ void ldsm4(uint32_t* r, uint32_t addr) {
    asm volatile("ldmatrix.sync.aligned.m8n8.x4.shared.b16 {%0,%1,%2,%3}, [%4];"
        : "=r"(r[0]), "=r"(r[1]), "=r"(r[2]), "=r"(r[3]) : "r"(addr));
}
__device__ __forceinline__ void ldsm4t(uint32_t* r, uint32_t addr) {
    asm volatile("ldmatrix.sync.aligned.m8n8.x4.trans.shared.b16 {%0,%1,%2,%3}, [%4];"
        : "=r"(r[0]), "=r"(r[1]), "=r"(r[2]), "=r"(r[3]) : "r"(addr));
}
__device__ __forceinline__ void mma16816(float* c, const uint32_t* a, const uint32_t* b) {
    asm volatile("mma.sync.aligned.m16n8k16.row.col.f32.bf16.bf16.f32 "
        "{%0,%1,%2,%3}, {%4,%5,%6,%7}, {%8,%9}, {%0,%1,%2,%3};"
        : "+f"(c[0]), "+f"(c[1]), "+f"(c[2]), "+f"(c[3])
        : "r"(a[0]), "r"(a[1]), "r"(a[2]), "r"(a[3]), "r"(b[0]), "r"(b[1]));
}
__device__ __forceinline__ void cpasync16(uint32_t dst, const void* src, int srcsize) {
    asm volatile("cp.async.cg.shared.global [%0], [%1], 16, %2;"
        :: "r"(dst), "l"(src), "r"(srcsize) : "memory");
}
#define CP_COMMIT() asm volatile("cp.async.commit_group;" ::: "memory")
#define CP_WAIT0()  asm volatile("cp.async.wait_group 0;" ::: "memory")
#define CP_WAIT1()  asm volatile("cp.async.wait_group 1;" ::: "memory")
__device__ __forceinline__ void bfsplit2(float x, float y, uint32_t& hi, uint32_t& lo) {
    __nv_bfloat162 h2, l2;
    h2.x = __float2bfloat16(x); h2.y = __float2bfloat16(y);
    l2.x = __float2bfloat16(x - __bfloat162float(h2.x));
    l2.y = __float2bfloat16(y - __bfloat162float(h2.y));
    hi = *(uint32_t*)&h2; lo = *(uint32_t*)&l2;
}

// ================= scratch =================
__device__ __nv_bfloat16 g_xh[BB*TE*DIMM];
__device__ __nv_bfloat16 g_xl[BB*TE*DIMM];
__device__ __nv_bfloat16 g_wqkvh[DIMM*DIMM];
__device__ __nv_bfloat16 g_wqkvl[DIMM*DIMM];
__device__ __nv_bfloat16 g_wsh[NSSM*DD*DIMM];
__device__ __nv_bfloat16 g_wsl[NSSM*DD*DIMM];
__device__ __nv_bfloat16 g_wph[DIMM*DIMM];
__device__ __nv_bfloat16 g_wpl[DIMM*DIMM];
__device__ __nv_bfloat16 g_cath[BB*TT*DIMM];
__device__ __nv_bfloat16 g_catl[BB*TT*DIMM];
__device__ __nv_bfloat16 g_qh[BB*NATTN*TE*DD];
__device__ __nv_bfloat16 g_ql[BB*NATTN*TE*DD];
__device__ __nv_bfloat16 g_kh[BB*NKV*TE*DD];
__device__ __nv_bfloat16 g_kl[BB*NKV*TE*DD];
__device__ __nv_bfloat16 g_vh[BB*NKV*TE*DD];
__device__ __nv_bfloat16 g_vl[BB*NKV*TE*DD];
__device__ float  g_qkv [BB*TE*DIMM];
__device__ float  g_ssmx[BB*TT*NSSM*DD];
__device__ float2 g_au  [BB*NSSM*TT*SS];
__device__ float  g_cc  [BB*NSSM*TT*SS];
__device__ float  g_hbuf[BB*NSSM*TT*SS];

// ================= fused conversion =================
#define CV_XN (BB*TE*DIMM)
#define CV_W1 (DIMM*DIMM)
#define CV_W2 (NSSM*DD*DIMM)
#define CV_W3 (DIMM*DIMM)
__global__ void conv_all_kernel(const float* __restrict__ x, const float* __restrict__ meta,
                                const float* __restrict__ qw, const float* __restrict__ kw,
                                const float* __restrict__ vw, const float* __restrict__ sw,
                                const float* __restrict__ pw)
{
    int idx = blockIdx.x*256 + threadIdx.x;
    float v; __nv_bfloat16 *dh, *dl; int off;
    if (idx < CV_XN) {
        int c = idx & 1023, row = idx >> 10;
        int b = row / TE, t = row % TE;
        v = (t < NMETA) ? meta[t*DIMM + c] : x[((size_t)(b*TT) + (t-NMETA))*DIMM + c];
        dh = g_xh; dl = g_xl; off = idx;
    } else if (idx < CV_XN + CV_W1) {
        int j = idx - CV_XN; int r = j >> 10, c = j & 1023;
        if (r < 512)      v = qw[r*DIMM + c];
        else if (r < 768) v = kw[(r-512)*DIMM + c];
        else              v = vw[(r-768)*DIMM + c];
        dh = g_wqkvh; dl = g_wqkvl; off = j;
    } else if (idx < CV_XN + CV_W1 + CV_W2) {
        int j = idx - CV_XN - CV_W1;
        v = sw[j]; dh = g_wsh; dl = g_wsl; off = j;
    } else if (idx < CV_XN + CV_W1 + CV_W2 + CV_W3) {
        int j = idx - CV_XN - CV_W1 - CV_W2;
        v = pw[j]; dh = g_wph; dl = g_wpl; off = j;
    } else return;
    __nv_bfloat16 h = __float2bfloat16(v);
    dh[off] = h;
    dl[off] = __float2bfloat16(v - __bfloat162float(h));
}

// ================= HMMA GEMM, 3xBF16 compensated, 2-stage pipelined =================
__global__ void __launch_bounds__(256, 2) gemm_mma_kernel(
    const __nv_bfloat16* __restrict__ Ah, const __nv_bfloat16* __restrict__ Al,
    const __nv_bfloat16* __restrict__ Bh, const __nv_bfloat16* __restrict__ Bl,
    float* __restrict__ C, int M, int N, int remap)
{
    extern __shared__ char smc[];
    const uint32_t smb = smem_u32(smc);
    const int tid = threadIdx.x, l = tid & 31, w = tid >> 5;
    const int wm = w & 3, wn = w >> 2;
    const int m0 = blockIdx.y << 7, n0 = blockIdx.x << 7;

    float acc[2][8][4];
#pragma unroll
    for (int mi = 0; mi < 2; mi++)
#pragma unroll
        for (int nf = 0; nf < 8; nf++)
#pragma unroll
            for (int q = 0; q < 4; q++) acc[mi][nf][q] = 0.f;

    auto fill = [&](int st, int c) {
        for (int i = tid; i < 2048; i += 256) {
            int tile = i >> 10, idx = i & 1023, row = idx >> 3, seg = idx & 7;
            uint32_t dst = smb + st*32768 + tile*16384 + row*128 + ((seg*16) ^ ((row & 7) << 4));
            const __nv_bfloat16* base;
            int grow, ok = 1;
            if (tile == 0) {
                grow = m0 + row;
                ok = grow < M;
                if (!ok) grow = 0;
                else if (remap) grow += 4*((grow >> 11) + 1);
                base = (seg < 4) ? Ah : Al;
            } else {
                grow = n0 + row;
                base = (seg < 4) ? Bh : Bl;
            }
            const void* src = base + ((size_t)grow << 10) + c*32 + (seg & 3)*8;
            cpasync16(dst, src, ok ? 16 : 0);
        }
        CP_COMMIT();
    };

    fill(0, 0);
    for (int c = 0; c < 32; c++) {
        const int st = c & 1;
        CP_WAIT0();
        __syncthreads();
        if (c + 1 < 32) fill(st ^ 1, c + 1);

        const uint32_t sA = smb + st*32768;
        const uint32_t sB = sA + 16384;
#pragma unroll
        for (int kk = 0; kk < 2; kk++) {
            uint32_t aH[2][4], aL[2][4], b[8][2];
#pragma unroll
            for (int mi = 0; mi < 2; mi++) {
                int row = wm*32 + mi*16 + (l & 15);
                int kb = kk*32 + ((l >> 4) << 4);
                uint32_t sw = (uint32_t)((row & 7) << 4);
                ldsm4(aH[mi], sA + row*128 + (kb ^ sw));
                ldsm4(aL[mi], sA + row*128 + ((kb + 64) ^ sw));
            }
#pragma unroll
            for (int nj = 0; nj < 4; nj++) {
                int row = wn*64 + nj*16 + (l & 7) + ((l >> 4) << 3);
                int kb = kk*32 + (((l >> 3) & 1) << 4);
                uint32_t t[4];
                ldsm4(t, sB + row*128 + (kb ^ ((row & 7) << 4)));
                b[nj*2][0]=t[0]; b[nj*2][1]=t[1]; b[nj*2+1][0]=t[2]; b[nj*2+1][1]=t[3];
            }
#pragma unroll
            for (int mi = 0; mi < 2; mi++)
#pragma unroll
                for (int nf = 0; nf < 8; nf++) {
                    mma16816(acc[mi][nf], aH[mi], b[nf]);
                    mma16816(acc[mi][nf], aL[mi], b[nf]);
                }
#pragma unroll
            for (int nj = 0; nj < 4; nj++) {
                int row = wn*64 + nj*16 + (l & 7) + ((l >> 4) << 3);
                int kb = kk*32 + (((l >> 3) & 1) << 4);
                uint32_t t[4];
                ldsm4(t, sB + row*128 + ((kb + 64) ^ ((row & 7) << 4)));
                b[nj*2][0]=t[0]; b[nj*2][1]=t[1]; b[nj*2+1][0]=t[2]; b[nj*2+1][1]=t[3];
            }
#pragma unroll
            for (int mi = 0; mi < 2; mi++)
#pragma unroll
                for (int nf = 0; nf < 8; nf++)
                    mma16816(acc[mi][nf], aH[mi], b[nf]);
        }
        __syncthreads();
    }

#pragma unroll
    for (int mi = 0; mi < 2; mi++) {
        int m = m0 + wm*32 + mi*16 + (l >> 2);
#pragma unroll
        for (int nf = 0; nf < 8; nf++) {
            int n = n0 + wn*64 + nf*8 + ((l & 3) << 1);
            if (m < M)
                *(float2*)&C[(size_t)m*N + n] = make_float2(acc[mi][nf][0], acc[mi][nf][1]);
            if (m + 8 < M)
                *(float2*)&C[(size_t)(m+8)*N + n] = make_float2(acc[mi][nf][2], acc[mi][nf][3]);
        }
    }
}

// ================= RMSNorm + RoPE (+q_gain) -> bf16 hi/lo; V convert =================
__global__ void normrot_kernel(const float* __restrict__ qgain)
{
    const int QROWS = BB*NATTN*TE;
    const int KROWS = BB*NKV*TE;
    const int VROWS = BB*NKV*TE;
    int gw = (blockIdx.x*blockDim.x + threadIdx.x) >> 5;
    int lane = threadIdx.x & 31;
    if (gw >= QROWS + KROWS + VROWS) return;

    if (gw < QROWS + KROWS) {
        const float* src; __nv_bfloat16 *dh, *dl; size_t doff; float gain; int t;
        if (gw < QROWS) {
            int b = gw / (NATTN*TE); int r = gw % (NATTN*TE); int h = r / TE; t = r % TE;
            src = &g_qkv[((size_t)(b*TE)+t)*DIMM + h*DD];
            doff = (((size_t)(b*NATTN+h))*TE + t)*DD;
            dh = g_qh; dl = g_ql;
            gain = qgain[h];
        } else {
            int w2 = gw - QROWS;
            int b = w2 / (NKV*TE); int r = w2 % (NKV*TE); int h = r / TE; t = r % TE;
            src = &g_qkv[((size_t)(b*TE)+t)*DIMM + 512 + h*DD];
            doff = (((size_t)(b*NKV+h))*TE + t)*DD;
            dh = g_kh; dl = g_kl;
            gain = 1.0f;
        }
        float x1 = src[lane], x2 = src[lane+32];
        float ss = x1*x1 + x2*x2;
#pragma unroll
        for (int o = 16; o > 0; o >>= 1) ss += __shfl_xor_sync(0xffffffffu, ss, o);
        float rinv = rsqrtf(ss*(1.0f/64.0f) + 1e-6f);
        x1 *= rinv; x2 *= rinv;
        float inv = expf(-(float)lane * 0.28782313662425575f);
        float f = (float)t * inv;
        float sn, cs; sincosf(f, &sn, &cs);
        float y1 = (x1*cs - x2*sn) * gain;
        float y2 = (x1*sn + x2*cs) * gain;
        __nv_bfloat16 h1 = __float2bfloat16(y1), h2 = __float2bfloat16(y2);
        dh[doff + lane]      = h1;
        dh[doff + lane + 32] = h2;
        dl[doff + lane]      = __float2bfloat16(y1 - __bfloat162float(h1));
        dl[doff + lane + 32] = __float2bfloat16(y2 - __bfloat162float(h2));
    } else {
        int w2 = gw - QROWS - KROWS;
        int b = w2 / (NKV*TE); int r = w2 % (NKV*TE); int h = r / TE; int t = r % TE;
        const float* src = &g_qkv[((size_t)(b*TE)+t)*DIMM + 768 + h*DD];
        size_t doff = (((size_t)(b*NKV+h))*TE + t)*DD;
        float v1 = src[lane], v2 = src[lane+32];
        __nv_bfloat16 h1 = __float2bfloat16(v1), h2 = __float2bfloat16(v2);
        g_vh[doff + lane]      = h1;
        g_vh[doff + lane + 32] = h2;
        g_vl[doff + lane]      = __float2bfloat16(v1 - __bfloat162float(h1));
        g_vl[doff + lane + 32] = __float2bfloat16(v2 - __bfloat162float(h2));
    }
}

// ================= HMMA flash attention, pipelined K/V loads =================
__global__ void __launch_bounds__(128) attn_mma_kernel(const float* __restrict__ attn_scale)
{
    extern __shared__ char smc[];
    const uint32_t smb = smem_u32(smc);
    const int b = blockIdx.z, h = blockIdx.y;
    const int qt = (int)(gridDim.x - 1 - blockIdx.x);
    const int q0 = qt << 6;
    const int hkv = h >> 1;
    const int tid = threadIdx.x, l = tid & 31, w = tid >> 5;

    const size_t qbase = ((size_t)(b*NATTN+h))*TE;
    const size_t kvbase = ((size_t)(b*NKV+hkv))*TE;

    auto loadK = [&](int k0) {
        for (int i = tid; i < 1024; i += 128) {
            int tile = i >> 9, idx = i & 511, row = idx >> 3, seg = idx & 7;
            uint32_t dst = smb + 16384 + tile*8192 + row*128 + ((seg*16) ^ ((row & 7) << 4));
            int krow = k0 + row;
            int ok = krow < TE;
            const __nv_bfloat16* base = tile ? g_kl : g_kh;
            cpasync16(dst, base + (kvbase + (ok ? krow : 0))*DD + seg*8, ok ? 16 : 0);
        }
        CP_COMMIT();
    };
    auto loadV = [&](int k0) {
        for (int i = tid; i < 1024; i += 128) {
            int tile = i >> 9, idx = i & 511, row = idx >> 3, seg = idx & 7;
            uint32_t dst = smb + 32768 + tile*8192 + row*128 + ((seg*16) ^ ((row & 7) << 4));
            int krow = k0 + row;
            int ok = krow < TE;
            const __nv_bfloat16* base = tile ? g_vl : g_vh;
            cpasync16(dst, base + (kvbase + (ok ? krow : 0))*DD + seg*8, ok ? 16 : 0);
        }
        CP_COMMIT();
    };

    {
        for (int i = tid; i < 1024; i += 128) {
            int tile = i >> 9, idx = i & 511, row = idx >> 3, seg = idx & 7;
            uint32_t dst = smb + tile*8192 + row*128 + ((seg*16) ^ ((row & 7) << 4));
            int qrow = q0 + row;
            int ok = qrow < TE;
            const __nv_bfloat16* base = tile ? g_ql : g_qh;
            cpasync16(dst, base + (qbase + (ok ? qrow : 0))*DD + seg*8, ok ? 16 : 0);
        }
        for (int i = tid; i < 1024; i += 128) {
            int tile = i >> 9, idx = i & 511, row = idx >> 3, seg = idx & 7;
            uint32_t dst = smb + 16384 + tile*8192 + row*128 + ((seg*16) ^ ((row & 7) << 4));
            int krow = row;
            const __nv_bfloat16* base = tile ? g_kl : g_kh;
            cpasync16(dst, base + (kvbase + krow)*DD + seg*8, 16);
        }
        CP_COMMIT();
        loadV(0);
    }

    float sO[8][4];
#pragma unroll
    for (int nf = 0; nf < 8; nf++)
#pragma unroll
        for (int q = 0; q < 4; q++) sO[nf][q] = 0.f;
    float m0r = -1e30f, m1r = -1e30f, l0r = 0.f, l1r = 0.f;

    const int grow0 = q0 + w*16 + (l >> 2);
    const int grow1 = grow0 + 8;

    for (int kt = 0; kt <= qt; kt++) {
        const int k0 = kt << 6;
        CP_WAIT1();
        __syncthreads();

        float s[8][4];
#pragma unroll
        for (int nf = 0; nf < 8; nf++)
#pragma unroll
            for (int q = 0; q < 4; q++) s[nf][q] = 0.f;

#pragma unroll
        for (int kc = 0; kc < 4; kc++) {
            uint32_t aH[4], aL[4], bk[8][2];
            {
                int row = w*16 + (l & 15);
                int kb = kc*32 + ((l >> 4) << 4);
                uint32_t ad = smb + row*128 + (kb ^ ((row & 7) << 4));
                ldsm4(aH, ad);
                ldsm4(aL, ad + 8192);
            }
#pragma unroll
            for (int nj = 0; nj < 4; nj++) {
                int row = nj*16 + (l & 7) + ((l >> 4) << 3);
                int kb = kc*32 + (((l >> 3) & 1) << 4);
                uint32_t bd = smb + 16384 + row*128 + (kb ^ ((row & 7) << 4));
                uint32_t t[4];
                ldsm4(t, bd);
                bk[nj*2][0]=t[0]; bk[nj*2][1]=t[1]; bk[nj*2+1][0]=t[2]; bk[nj*2+1][1]=t[3];
            }
#pragma unroll
            for (int nf = 0; nf < 8; nf++) {
                mma16816(s[nf], aH, bk[nf]);
                mma16816(s[nf], aL, bk[nf]);
            }
#pragma unroll
            for (int nj = 0; nj < 4; nj++) {
                int row = nj*16 + (l & 7) + ((l >> 4) << 3);
                int kb = kc*32 + (((l >> 3) & 1) << 4);
                uint32_t bd = smb + 24576 + row*128 + (kb ^ ((row & 7) << 4));
                uint32_t t[4];
                ldsm4(t, bd);
                bk[nj*2][0]=t[0]; bk[nj*2][1]=t[1]; bk[nj*2+1][0]=t[2]; bk[nj*2+1][1]=t[3];
            }
#pragma unroll
            for (int nf = 0; nf < 8; nf++)
                mma16816(s[nf], aH, bk[nf]);
        }
        __syncthreads();
        if (kt < qt) loadK(k0 + 64);

        const bool diag = (kt == qt);
#pragma unroll
        for (int nf = 0; nf < 8; nf++) {
            int c0 = k0 + nf*8 + ((l & 3) << 1);
            s[nf][0] *= 0.125f; s[nf][1] *= 0.125f;
            s[nf][2] *= 0.125f; s[nf][3] *= 0.125f;
            if (diag) {
                if (c0     > grow0) s[nf][0] = -1e30f;
                if (c0 + 1 > grow0) s[nf][1] = -1e30f;
                if (c0     > grow1) s[nf][2] = -1e30f;
                if (c0 + 1 > grow1) s[nf][3] = -1e30f;
            }
        }

        float mx0 = -1e30f, mx1 = -1e30f;
#pragma unroll
        for (int nf = 0; nf < 8; nf++) {
            mx0 = fmaxf(mx0, fmaxf(s[nf][0], s[nf][1]));
            mx1 = fmaxf(mx1, fmaxf(s[nf][2], s[nf][3]));
        }
        mx0 = fmaxf(mx0, __shfl_xor_sync(0xffffffffu, mx0, 1));
        mx0 = fmaxf(mx0, __shfl_xor_sync(0xffffffffu, mx0, 2));
        mx1 = fmaxf(mx1, __shfl_xor_sync(0xffffffffu, mx1, 1));
        mx1 = fmaxf(mx1, __shfl_xor_sync(0xffffffffu, mx1, 2));
        float mn0 = fmaxf(m0r, mx0), mn1 = fmaxf(m1r, mx1);
        float al0 = __expf(m0r - mn0), al1 = __expf(m1r - mn1);
        m0r = mn0; m1r = mn1;

        float rs0 = 0.f, rs1 = 0.f;
#pragma unroll
        for (int nf = 0; nf < 8; nf++) {
            float p0 = __expf(s[nf][0] - mn0), p1 = __expf(s[nf][1] - mn0);
            float p2 = __expf(s[nf][2] - mn1), p3 = __expf(s[nf][3] - mn1);
            rs0 += p0 + p1; rs1 += p2 + p3;
            s[nf][0] = p0; s[nf][1] = p1; s[nf][2] = p2; s[nf][3] = p3;
        }
        rs0 += __shfl_xor_sync(0xffffffffu, rs0, 1);
        rs0 += __shfl_xor_sync(0xffffffffu, rs0, 2);
        rs1 += __shfl_xor_sync(0xffffffffu, rs1, 1);
        rs1 += __shfl_xor_sync(0xffffffffu, rs1, 2);
        l0r = l0r*al0 + rs0;
        l1r = l1r*al1 + rs1;

#pragma unroll
        for (int nf = 0; nf < 8; nf++) {
            sO[nf][0] *= al0; sO[nf][1] *= al0;
            sO[nf][2] *= al1; sO[nf][3] *= al1;
        }

        if (kt < qt) { CP_WAIT1(); } else { CP_WAIT0(); }
        __syncthreads();

#pragma unroll
        for (int kc = 0; kc < 4; kc++) {
            uint32_t pH[4], pL[4], bv[8][2];
            bfsplit2(s[2*kc][0],   s[2*kc][1],   pH[0], pL[0]);
            bfsplit2(s[2*kc][2],   s[2*kc][3],   pH[1], pL[1]);
            bfsplit2(s[2*kc+1][0], s[2*kc+1][1], pH[2], pL[2]);
            bfsplit2(s[2*kc+1][2], s[2*kc+1][3], pH[3], pL[3]);
#pragma unroll
            for (int i2 = 0; i2 < 4; i2++) {
                int row = kc*16 + (l & 7) + (((l >> 3) & 1) << 3);
                int cb = i2*32 + (((l >> 4) & 1) << 4);
                uint32_t vd = smb + 32768 + row*128 + (cb ^ ((row & 7) << 4));
                uint32_t t[4];
                ldsm4t(t, vd);
                bv[2*i2][0]=t[0]; bv[2*i2][1]=t[1]; bv[2*i2+1][0]=t[2]; bv[2*i2+1][1]=t[3];
            }
#pragma unroll
            for (int nf = 0; nf < 8; nf++) {
                mma16816(sO[nf], pH, bv[nf]);
                mma16816(sO[nf], pL, bv[nf]);
            }
#pragma unroll
            for (int i2 = 0; i2 < 4; i2++) {
                int row = kc*16 + (l & 7) + (((l >> 3) & 1) << 3);
                int cb = i2*32 + (((l >> 4) & 1) << 4);
                uint32_t vd = smb + 40960 + row*128 + (cb ^ ((row & 7) << 4));
                uint32_t t[4];
                ldsm4t(t, vd);
                bv[2*i2][0]=t[0]; bv[2*i2][1]=t[1]; bv[2*i2+1][0]=t[2]; bv[2*i2+1][1]=t[3];
            }
#pragma unroll
            for (int nf = 0; nf < 8; nf++)
                mma16816(sO[nf], pH, bv[nf]);
        }
        __syncthreads();
        if (kt < qt) loadV(k0 + 64);
    }

    float ascale = attn_scale[0];
    float inv0 = ascale / l0r, inv1 = ascale / l1r;
#pragma unroll
    for (int nf = 0; nf < 8; nf++) {
        int oc = h*DD + nf*8 + ((l & 3) << 1);
        if (grow0 >= NMETA && grow0 < TE) {
            float v0 = sO[nf][0]*inv0, v1 = sO[nf][1]*inv0;
            uint32_t hi, lo; bfsplit2(v0, v1, hi, lo);
            size_t base = ((size_t)(b*TT) + (grow0 - NMETA))*DIMM + oc;
            *(uint32_t*)&g_cath[base] = hi;
            *(uint32_t*)&g_catl[base] = lo;
        }
        if (grow1 >= NMETA && grow1 < TE) {
            float v2 = sO[nf][2]*inv1, v3 = sO[nf][3]*inv1;
            uint32_t hi, lo; bfsplit2(v2, v3, hi, lo);
            size_t base = ((size_t)(b*TT) + (grow1 - NMETA))*DIMM + oc;
            *(uint32_t*)&g_cath[base] = hi;
            *(uint32_t*)&g_catl[base] = lo;
        }
    }
}

// ================= SSM: dt / a / Bx / Cc =================
__global__ void dtbc_kernel(const float* __restrict__ dtw, const float* __restrict__ dtb,
                            const float* __restrict__ Bw,  const float* __restrict__ Cw,
                            const float* __restrict__ logA)
{
    __shared__ float xs[64][65];
    __shared__ float ws[48][65];
    __shared__ float dts[64][16];
    const int b = blockIdx.z, h = blockIdx.y, t0 = blockIdx.x*64;
    const int tid = threadIdx.x;

    for (int idx = tid; idx < 48*64; idx += 256) {
        int o = idx >> 6, k = idx & 63;
        float v;
        if (o < 16)      v = dtw[(h*16+o)*64 + k];
        else if (o < 32) v = Bw[(h*16+(o-16))*64 + k];
        else             v = Cw[(h*16+(o-32))*64 + k];
        ws[o][k] = v;
    }
    for (int idx = tid; idx < 64*64; idx += 256) {
        int r = idx >> 6, k = idx & 63;
        xs[r][k] = g_ssmx[((size_t)(b*TT)+t0+r)*(NSSM*DD) + h*DD + k];
    }
    __syncthreads();

    const int r = tid >> 2;
    const size_t obase = (((size_t)(b*NSSM+h))*TT + t0 + r)*SS;

    {
        int so = (tid & 3) << 2;
#pragma unroll
        for (int q = 0; q < 4; q++) {
            int o = so + q;
            float d = 0.f;
#pragma unroll
            for (int k = 0; k < 64; k++) d += xs[r][k]*ws[o][k];
            d += dtb[h*16 + o];
            float sp = (d > 20.f) ? d : log1pf(expf(d));
            float dt = fminf(sp, 1.0f);
            dts[r][o] = dt;
            float A  = fminf(-expf(logA[h*16 + o]), 10.0f);
            float la = fminf(fmaxf(dt*A, -0.5f), 0.0f);
            g_au[obase + o].x = expf(la);
        }
    }
    __syncthreads();
    {
        int jo = (tid & 3) << 3;
#pragma unroll
        for (int q = 0; q < 8; q++) {
            int o2 = jo + q;
            float d = 0.f;
#pragma unroll
            for (int k = 0; k < 64; k++) d += xs[r][k]*ws[16+o2][k];
            if (o2 < 16) g_au[obase + o2].y     = d * dts[r][o2];
            else         g_cc[obase + (o2-16)]  = d;
        }
    }
}

// ================= chunk-parallel scan =================
__global__ void scan_kernel()
{
    const int bh = blockIdx.x;
    const int s = threadIdx.x & 15, ck = threadIdx.x >> 4;
    const size_t base = (size_t)bh*TT*SS;
    __shared__ float sc_c[16][17], sc_p[16][17], sc_in[16][17];

    const int t0 = ck*128;
    float hv = 0.f, p = 1.f;
    for (int t = 0; t < 128; t++) {
        float2 au = g_au[base + (size_t)(t0+t)*SS + s];
        hv = fmaf(au.x, hv, au.y);
        p *= au.x;
        g_hbuf[base + (size_t)(t0+t)*SS + s] = hv;
    }
    sc_c[ck][s] = hv; sc_p[ck][s] = p;
    __syncthreads();
    if (threadIdx.x < 16) {
        int s2 = threadIdx.x;
        float hin = 0.f;
        for (int c2 = 0; c2 < 16; c2++) {
            sc_in[c2][s2] = hin;
            hin = sc_c[c2][s2] + sc_p[c2][s2]*hin;
        }
    }
    __syncthreads();
    float hin = sc_in[ck][s];
    if (ck > 0) {
        p = 1.f;
        for (int t = 0; t < 128; t++) {
            float2 au = g_au[base + (size_t)(t0+t)*SS + s];
            p *= au.x;
            g_hbuf[base + (size_t)(t0+t)*SS + s] += p*hin;
        }
    }
}

// ================= SSM epilogue =================
__global__ void ssmout_kernel(const float* __restrict__ Ow, const float* __restrict__ ssm_scale)
{
    __shared__ float hs[64][17];
    __shared__ float cs[64][17];
    __shared__ float ows[64][17];
    const int b = blockIdx.z, h = blockIdx.y, t0 = blockIdx.x*64;
    const int tid = threadIdx.x;

    for (int idx = tid; idx < 64*16; idx += 256) {
        int r = idx >> 4, s = idx & 15;
        size_t src = (((size_t)(b*NSSM+h))*TT + t0 + r)*SS + s;
        hs[r][s] = g_hbuf[src];
        cs[r][s] = g_cc[src];
        ows[r][s] = Ow[(h*64 + r)*16 + s];
    }
    __syncthreads();

    const int r = tid >> 2, dp = tid & 3;
    float y = 0.f;
#pragma unroll
    for (int s = 0; s < 16; s++) y += cs[r][s]*hs[r][s];
    float x0 = g_ssmx[((size_t)(b*TT)+t0+r)*(NSSM*DD) + h*DD];
    float sc = ssm_scale[0];
    float yx = y * x0;
    size_t ob = ((size_t)(b*TT)+t0+r)*DIMM + 512 + h*DD + dp*16;
#pragma unroll
    for (int q = 0; q < 16; q++) {
        int d = dp*16 + q;
        float v = yx;
#pragma unroll
        for (int s = 0; s < 16; s++) v += hs[r][s]*ows[d][s];
        v *= sc;
        __nv_bfloat16 hh = __float2bfloat16(v);
        g_cath[ob + q] = hh;
        g_catl[ob + q] = __float2bfloat16(v - __bfloat162float(hh));
    }
}

// ================= launch =================
extern "C" void kernel_launch(void* const* d_in, const int* in_sizes, int n_in,
                              void* d_out, int out_size)
{
    const float* x         = (const float*)d_in[0];
    const float* meta      = (const float*)d_in[1];
    const float* qw        = (const float*)d_in[2];
    const float* kw        = (const float*)d_in[3];
    const float* vw        = (const float*)d_in[4];
    const float* qgain     = (const float*)d_in[5];
    const float* ssm_in_w  = (const float*)d_in[6];
    const float* projw     = (const float*)d_in[7];
    const float* attn_sc   = (const float*)d_in[8];
    const float* ssm_sc    = (const float*)d_in[9];
    const float* logA      = (const float*)d_in[10];
    const float* Bw        = (const float*)d_in[11];
    const float* Cw        = (const float*)d_in[12];
    const float* dtw       = (const float*)d_in[13];
    const float* dtb       = (const float*)d_in[14];
    const float* Ow        = (const float*)d_in[15];
    float* out = (float*)d_out;

    __nv_bfloat16 *p_xh, *p_xl, *p_wqh, *p_wql, *p_wsh, *p_wsl, *p_wph, *p_wpl, *p_cth, *p_ctl;
    float *p_qkv, *p_ssmx;
    cudaGetSymbolAddress((void**)&p_xh,  g_xh);
    cudaGetSymbolAddress((void**)&p_xl,  g_xl);
    cudaGetSymbolAddress((void**)&p_wqh, g_wqkvh);
    cudaGetSymbolAddress((void**)&p_wql, g_wqkvl);
    cudaGetSymbolAddress((void**)&p_wsh, g_wsh);
    cudaGetSymbolAddress((void**)&p_wsl, g_wsl);
    cudaGetSymbolAddress((void**)&p_wph, g_wph);
    cudaGetSymbolAddress((void**)&p_wpl, g_wpl);
    cudaGetSymbolAddress((void**)&p_cth, g_cath);
    cudaGetSymbolAddress((void**)&p_ctl, g_catl);
    cudaGetSymbolAddress((void**)&p_qkv,  g_qkv);
    cudaGetSymbolAddress((void**)&p_ssmx, g_ssmx);

    const int GEMM_SMEM = 2*32768;
    cudaFuncSetAttribute(gemm_mma_kernel, cudaFuncAttributeMaxDynamicSharedMemorySize, GEMM_SMEM);
    const int ATTN_SMEM = 6*8192;
    cudaFuncSetAttribute(attn_mma_kernel, cudaFuncAttributeMaxDynamicSharedMemorySize, ATTN_SMEM);

    // one-time host-side stream/event resources (no device memory involved);
    // created on the first (uncaptured) correctness call, reused thereafter
    static cudaStream_t s_ssm = nullptr;
    static cudaEvent_t  ev_conv = nullptr, ev_ssm = nullptr;
    if (s_ssm == nullptr) {
        cudaStreamCreateWithFlags(&s_ssm, cudaStreamNonBlocking);
        cudaEventCreateWithFlags(&ev_conv, cudaEventDisableTiming);
        cudaEventCreateWithFlags(&ev_ssm,  cudaEventDisableTiming);
    }

    const int CV_TOTAL = CV_XN + CV_W1 + CV_W2 + CV_W3;

    // ---- main stream: conversion ----
    conv_all_kernel<<<(CV_TOTAL + 255)/256, 256>>>(x, meta, qw, kw, vw, ssm_in_w, projw);
    cudaEventRecord(ev_conv, 0);

    // ---- SSM branch on side stream (independent of attention chain) ----
    cudaStreamWaitEvent(s_ssm, ev_conv, 0);
    gemm_mma_kernel<<<dim3((NSSM*DD)/128, (BB*TT)/128), 256, GEMM_SMEM, s_ssm>>>(
        p_xh, p_xl, p_wsh, p_wsl, p_ssmx, BB*TT, NSSM*DD, 1);
    dtbc_kernel<<<dim3(TT/64, NSSM, BB), 256, 0, s_ssm>>>(dtw, dtb, Bw, Cw, logA);
    scan_kernel<<<BB*NSSM, 256, 0, s_ssm>>>();
    ssmout_kernel<<<dim3(TT/64, NSSM, BB), 256, 0, s_ssm>>>(Ow, ssm_sc);
    cudaEventRecord(ev_ssm, s_ssm);

    // ---- attention chain on main stream ----
    gemm_mma_kernel<<<dim3(DIMM/128, (BB*TE + 127)/128), 256, GEMM_SMEM>>>(
        p_xh, p_xl, p_wqh, p_wql, p_qkv, BB*TE, DIMM, 0);
    {
        int warps = BB*(NATTN + NKV + NKV)*TE;
        normrot_kernel<<<(warps*32 + 255)/256, 256>>>(qgain);
    }
    attn_mma_kernel<<<dim3((TE + 63)/64, NATTN, BB), 128, ATTN_SMEM>>>(attn_sc);

    // ---- join, then output projection ----
    cudaStreamWaitEvent(0, ev_ssm, 0);
    gemm_mma_kernel<<<dim3(DIMM/128, (BB*TT)/128), 256, GEMM_SMEM>>>(
        p_cth, p_ctl, p_wph, p_wpl, out, BB*TT, DIMM, 0);
}

// round 11
// speedup vs baseline: 1.3418x; 1.3418x over previous
#include <cuda_runtime.h>
#include <cuda_bf16.h>
#include <math.h>
#include <stdint.h>

#define BB     2
#define TT     2048
#define TE     2052
#define DIMM   1024
#define DD     64
#define NATTN  8
#define NKV    4
#define NSSM   8
#define SS     16
#define NMETA  4

// scan decomposition
#define SC_C   64      // chunks
#define SC_L   32      // steps per chunk

// ================= helpers =================
__device__ __forceinline__ uint32_t smem_u32(const void* p) {
    uint32_t a;
    asm("{ .reg .u64 t; cvta.to.shared.u64 t, %1; cvt.u32.u64 %0, t; }" : "=r"(a) : "l"(p));
    return a;
}
__device__ __forceinline__ void ldsm4(uint32_t* r, uint32_t addr) {
    asm volatile("ldmatrix.sync.aligned.m8n8.x4.shared.b16 {%0,%1,%2,%3}, [%4];"
        : "=r"(r[0]), "=r"(r[1]), "=r"(r[2]), "=r"(r[3]) : "r"(addr));
}
__device__ __forceinline__ void ldsm4t(uint32_t* r, uint32_t addr) {
    asm volatile("ldmatrix.sync.aligned.m8n8.x4.trans.shared.b16 {%0,%1,%2,%3}, [%4];"
        : "=r"(r[0]), "=r"(r[1]), "=r"(r[2]), "=r"(r[3]) : "r"(addr));
}
__device__ __forceinline__ void mma16816(float* c, const uint32_t* a, const uint32_t* b) {
    asm volatile("mma.sync.aligned.m16n8k16.row.col.f32.bf16.bf16.f32 "
        "{%0,%1,%2,%3}, {%4,%5,%6,%7}, {%8,%9}, {%0,%1,%2,%3};"
        : "+f"(c[0]), "+f"(c[1]), "+f"(c[2]), "+f"(c[3])
        : "r"(a[0]), "r"(a[1]), "r"(a[2]), "r"(a[3]), "r"(b[0]), "r"(b[1]));
}
__device__ __forceinline__ void cpasync16(uint32_t dst, const void* src, int srcsize) {
    asm volatile("cp.async.cg.shared.global [%0], [%1], 16, %2;"
        :: "r"(dst), "l"(src), "r"(srcsize) : "memory");
}
#define CP_COMMIT() asm volatile("cp.async.commit_group;" ::: "memory")
#define CP_WAIT0()  asm volatile("cp.async.wait_group 0;" ::: "memory")
#define CP_WAIT1()  asm volatile("cp.async.wait_group 1;" ::: "memory")
__device__ __forceinline__ void bfsplit2(float x, float y, uint32_t& hi, uint32_t& lo) {
    __nv_bfloat162 h2, l2;
    h2.x = __float2bfloat16(x); h2.y = __float2bfloat16(y);
    l2.x = __float2bfloat16(x - __bfloat162float(h2.x));
    l2.y = __float2bfloat16(y - __bfloat162float(h2.y));
    hi = *(uint32_t*)&h2; lo = *(uint32_t*)&l2;
}

// ================= scratch =================
__device__ __nv_bfloat16 g_xh[BB*TE*DIMM];
__device__ __nv_bfloat16 g_xl[BB*TE*DIMM];
__device__ __nv_bfloat16 g_wqkvh[DIMM*DIMM];
__device__ __nv_bfloat16 g_wqkvl[DIMM*DIMM];
__device__ __nv_bfloat16 g_wsh[NSSM*DD*DIMM];
__device__ __nv_bfloat16 g_wsl[NSSM*DD*DIMM];
__device__ __nv_bfloat16 g_wph[DIMM*DIMM];
__device__ __nv_bfloat16 g_wpl[DIMM*DIMM];
__device__ __nv_bfloat16 g_cath[BB*TT*DIMM];
__device__ __nv_bfloat16 g_catl[BB*TT*DIMM];
__device__ __nv_bfloat16 g_qh[BB*NATTN*TE*DD];
__device__ __nv_bfloat16 g_ql[BB*NATTN*TE*DD];
__device__ __nv_bfloat16 g_kh[BB*NKV*TE*DD];
__device__ __nv_bfloat16 g_kl[BB*NKV*TE*DD];
__device__ __nv_bfloat16 g_vh[BB*NKV*TE*DD];
__device__ __nv_bfloat16 g_vl[BB*NKV*TE*DD];
__device__ float  g_qkv [BB*TE*DIMM];
__device__ float  g_ssmx[BB*TT*NSSM*DD];
__device__ float2 g_au  [BB*NSSM*TT*SS];
__device__ float  g_cc  [BB*NSSM*TT*SS];
__device__ float  g_hbuf[BB*NSSM*TT*SS];
__device__ float  g_pp  [BB*NSSM*TT*SS];          // within-chunk prefix products
__device__ float2 g_carry[BB*NSSM*SS*SC_C];       // (h_last, p) per (lane, chunk)
__device__ float  g_hin [BB*NSSM*SS*SC_C];        // incoming h per (lane, chunk)

// ================= fused conversion =================
#define CV_XN (BB*TE*DIMM)
#define CV_W1 (DIMM*DIMM)
#define CV_W2 (NSSM*DD*DIMM)
#define CV_W3 (DIMM*DIMM)
__global__ void conv_all_kernel(const float* __restrict__ x, const float* __restrict__ meta,
                                const float* __restrict__ qw, const float* __restrict__ kw,
                                const float* __restrict__ vw, const float* __restrict__ sw,
                                const float* __restrict__ pw)
{
    int idx = blockIdx.x*256 + threadIdx.x;
    float v; __nv_bfloat16 *dh, *dl; int off;
    if (idx < CV_XN) {
        int c = idx & 1023, row = idx >> 10;
        int b = row / TE, t = row % TE;
        v = (t < NMETA) ? meta[t*DIMM + c] : x[((size_t)(b*TT) + (t-NMETA))*DIMM + c];
        dh = g_xh; dl = g_xl; off = idx;
    } else if (idx < CV_XN + CV_W1) {
        int j = idx - CV_XN; int r = j >> 10, c = j & 1023;
        if (r < 512)      v = qw[r*DIMM + c];
        else if (r < 768) v = kw[(r-512)*DIMM + c];
        else              v = vw[(r-768)*DIMM + c];
        dh = g_wqkvh; dl = g_wqkvl; off = j;
    } else if (idx < CV_XN + CV_W1 + CV_W2) {
        int j = idx - CV_XN - CV_W1;
        v = sw[j]; dh = g_wsh; dl = g_wsl; off = j;
    } else if (idx < CV_XN + CV_W1 + CV_W2 + CV_W3) {
        int j = idx - CV_XN - CV_W1 - CV_W2;
        v = pw[j]; dh = g_wph; dl = g_wpl; off = j;
    } else return;
    __nv_bfloat16 h = __float2bfloat16(v);
    dh[off] = h;
    dl[off] = __float2bfloat16(v - __bfloat162float(h));
}

// ================= HMMA GEMM, 3xBF16 compensated, 2-stage pipelined =================
__global__ void __launch_bounds__(256, 2) gemm_mma_kernel(
    const __nv_bfloat16* __restrict__ Ah, const __nv_bfloat16* __restrict__ Al,
    const __nv_bfloat16* __restrict__ Bh, const __nv_bfloat16* __restrict__ Bl,
    float* __restrict__ C, int M, int N, int remap)
{
    extern __shared__ char smc[];
    const uint32_t smb = smem_u32(smc);
    const int tid = threadIdx.x, l = tid & 31, w = tid >> 5;
    const int wm = w & 3, wn = w >> 2;
    const int m0 = blockIdx.y << 7, n0 = blockIdx.x << 7;

    float acc[2][8][4];
#pragma unroll
    for (int mi = 0; mi < 2; mi++)
#pragma unroll
        for (int nf = 0; nf < 8; nf++)
#pragma unroll
            for (int q = 0; q < 4; q++) acc[mi][nf][q] = 0.f;

    auto fill = [&](int st, int c) {
        for (int i = tid; i < 2048; i += 256) {
            int tile = i >> 10, idx = i & 1023, row = idx >> 3, seg = idx & 7;
            uint32_t dst = smb + st*32768 + tile*16384 + row*128 + ((seg*16) ^ ((row & 7) << 4));
            const __nv_bfloat16* base;
            int grow, ok = 1;
            if (tile == 0) {
                grow = m0 + row;
                ok = grow < M;
                if (!ok) grow = 0;
                else if (remap) grow += 4*((grow >> 11) + 1);
                base = (seg < 4) ? Ah : Al;
            } else {
                grow = n0 + row;
                base = (seg < 4) ? Bh : Bl;
            }
            const void* src = base + ((size_t)grow << 10) + c*32 + (seg & 3)*8;
            cpasync16(dst, src, ok ? 16 : 0);
        }
        CP_COMMIT();
    };

    fill(0, 0);
    for (int c = 0; c < 32; c++) {
        const int st = c & 1;
        CP_WAIT0();
        __syncthreads();
        if (c + 1 < 32) fill(st ^ 1, c + 1);

        const uint32_t sA = smb + st*32768;
        const uint32_t sB = sA + 16384;
#pragma unroll
        for (int kk = 0; kk < 2; kk++) {
            uint32_t aH[2][4], aL[2][4], b[8][2];
#pragma unroll
            for (int mi = 0; mi < 2; mi++) {
                int row = wm*32 + mi*16 + (l & 15);
                int kb = kk*32 + ((l >> 4) << 4);
                uint32_t sw = (uint32_t)((row & 7) << 4);
                ldsm4(aH[mi], sA + row*128 + (kb ^ sw));
                ldsm4(aL[mi], sA + row*128 + ((kb + 64) ^ sw));
            }
#pragma unroll
            for (int nj = 0; nj < 4; nj++) {
                int row = wn*64 + nj*16 + (l & 7) + ((l >> 4) << 3);
                int kb = kk*32 + (((l >> 3) & 1) << 4);
                uint32_t t[4];
                ldsm4(t, sB + row*128 + (kb ^ ((row & 7) << 4)));
                b[nj*2][0]=t[0]; b[nj*2][1]=t[1]; b[nj*2+1][0]=t[2]; b[nj*2+1][1]=t[3];
            }
#pragma unroll
            for (int mi = 0; mi < 2; mi++)
#pragma unroll
                for (int nf = 0; nf < 8; nf++) {
                    mma16816(acc[mi][nf], aH[mi], b[nf]);
                    mma16816(acc[mi][nf], aL[mi], b[nf]);
                }
#pragma unroll
            for (int nj = 0; nj < 4; nj++) {
                int row = wn*64 + nj*16 + (l & 7) + ((l >> 4) << 3);
                int kb = kk*32 + (((l >> 3) & 1) << 4);
                uint32_t t[4];
                ldsm4(t, sB + row*128 + ((kb + 64) ^ ((row & 7) << 4)));
                b[nj*2][0]=t[0]; b[nj*2][1]=t[1]; b[nj*2+1][0]=t[2]; b[nj*2+1][1]=t[3];
            }
#pragma unroll
            for (int mi = 0; mi < 2; mi++)
#pragma unroll
                for (int nf = 0; nf < 8; nf++)
                    mma16816(acc[mi][nf], aH[mi], b[nf]);
        }
        __syncthreads();
    }

#pragma unroll
    for (int mi = 0; mi < 2; mi++) {
        int m = m0 + wm*32 + mi*16 + (l >> 2);
#pragma unroll
        for (int nf = 0; nf < 8; nf++) {
            int n = n0 + wn*64 + nf*8 + ((l & 3) << 1);
            if (m < M)
                *(float2*)&C[(size_t)m*N + n] = make_float2(acc[mi][nf][0], acc[mi][nf][1]);
            if (m + 8 < M)
                *(float2*)&C[(size_t)(m+8)*N + n] = make_float2(acc[mi][nf][2], acc[mi][nf][3]);
        }
    }
}

// ================= RMSNorm + RoPE (+q_gain) -> bf16 hi/lo; V convert =================
__global__ void normrot_kernel(const float* __restrict__ qgain)
{
    const int QROWS = BB*NATTN*TE;
    const int KROWS = BB*NKV*TE;
    const int VROWS = BB*NKV*TE;
    int gw = (blockIdx.x*blockDim.x + threadIdx.x) >> 5;
    int lane = threadIdx.x & 31;
    if (gw >= QROWS + KROWS + VROWS) return;

    if (gw < QROWS + KROWS) {
        const float* src; __nv_bfloat16 *dh, *dl; size_t doff; float gain; int t;
        if (gw < QROWS) {
            int b = gw / (NATTN*TE); int r = gw % (NATTN*TE); int h = r / TE; t = r % TE;
            src = &g_qkv[((size_t)(b*TE)+t)*DIMM + h*DD];
            doff = (((size_t)(b*NATTN+h))*TE + t)*DD;
            dh = g_qh; dl = g_ql;
            gain = qgain[h];
        } else {
            int w2 = gw - QROWS;
            int b = w2 / (NKV*TE); int r = w2 % (NKV*TE); int h = r / TE; t = r % TE;
            src = &g_qkv[((size_t)(b*TE)+t)*DIMM + 512 + h*DD];
            doff = (((size_t)(b*NKV+h))*TE + t)*DD;
            dh = g_kh; dl = g_kl;
            gain = 1.0f;
        }
        float x1 = src[lane], x2 = src[lane+32];
        float ss = x1*x1 + x2*x2;
#pragma unroll
        for (int o = 16; o > 0; o >>= 1) ss += __shfl_xor_sync(0xffffffffu, ss, o);
        float rinv = rsqrtf(ss*(1.0f/64.0f) + 1e-6f);
        x1 *= rinv; x2 *= rinv;
        float inv = expf(-(float)lane * 0.28782313662425575f);
        float f = (float)t * inv;
        float sn, cs; sincosf(f, &sn, &cs);
        float y1 = (x1*cs - x2*sn) * gain;
        float y2 = (x1*sn + x2*cs) * gain;
        __nv_bfloat16 h1 = __float2bfloat16(y1), h2 = __float2bfloat16(y2);
        dh[doff + lane]      = h1;
        dh[doff + lane + 32] = h2;
        dl[doff + lane]      = __float2bfloat16(y1 - __bfloat162float(h1));
        dl[doff + lane + 32] = __float2bfloat16(y2 - __bfloat162float(h2));
    } else {
        int w2 = gw - QROWS - KROWS;
        int b = w2 / (NKV*TE); int r = w2 % (NKV*TE); int h = r / TE; int t = r % TE;
        const float* src = &g_qkv[((size_t)(b*TE)+t)*DIMM + 768 + h*DD];
        size_t doff = (((size_t)(b*NKV+h))*TE + t)*DD;
        float v1 = src[lane], v2 = src[lane+32];
        __nv_bfloat16 h1 = __float2bfloat16(v1), h2 = __float2bfloat16(v2);
        g_vh[doff + lane]      = h1;
        g_vh[doff + lane + 32] = h2;
        g_vl[doff + lane]      = __float2bfloat16(v1 - __bfloat162float(h1));
        g_vl[doff + lane + 32] = __float2bfloat16(v2 - __bfloat162float(h2));
    }
}

// ================= HMMA flash attention, pipelined K/V loads =================
__global__ void __launch_bounds__(128) attn_mma_kernel(const float* __restrict__ attn_scale)
{
    extern __shared__ char smc[];
    const uint32_t smb = smem_u32(smc);
    const int b = blockIdx.z, h = blockIdx.y;
    const int qt = (int)(gridDim.x - 1 - blockIdx.x);
    const int q0 = qt << 6;
    const int hkv = h >> 1;
    const int tid = threadIdx.x, l = tid & 31, w = tid >> 5;

    const size_t qbase = ((size_t)(b*NATTN+h))*TE;
    const size_t kvbase = ((size_t)(b*NKV+hkv))*TE;

    auto loadK = [&](int k0) {
        for (int i = tid; i < 1024; i += 128) {
            int tile = i >> 9, idx = i & 511, row = idx >> 3, seg = idx & 7;
            uint32_t dst = smb + 16384 + tile*8192 + row*128 + ((seg*16) ^ ((row & 7) << 4));
            int krow = k0 + row;
            int ok = krow < TE;
            const __nv_bfloat16* base = tile ? g_kl : g_kh;
            cpasync16(dst, base + (kvbase + (ok ? krow : 0))*DD + seg*8, ok ? 16 : 0);
        }
        CP_COMMIT();
    };
    auto loadV = [&](int k0) {
        for (int i = tid; i < 1024; i += 128) {
            int tile = i >> 9, idx = i & 511, row = idx >> 3, seg = idx & 7;
            uint32_t dst = smb + 32768 + tile*8192 + row*128 + ((seg*16) ^ ((row & 7) << 4));
            int krow = k0 + row;
            int ok = krow < TE;
            const __nv_bfloat16* base = tile ? g_vl : g_vh;
            cpasync16(dst, base + (kvbase + (ok ? krow : 0))*DD + seg*8, ok ? 16 : 0);
        }
        CP_COMMIT();
    };

    {
        for (int i = tid; i < 1024; i += 128) {
            int tile = i >> 9, idx = i & 511, row = idx >> 3, seg = idx & 7;
            uint32_t dst = smb + tile*8192 + row*128 + ((seg*16) ^ ((row & 7) << 4));
            int qrow = q0 + row;
            int ok = qrow < TE;
            const __nv_bfloat16* base = tile ? g_ql : g_qh;
            cpasync16(dst, base + (qbase + (ok ? qrow : 0))*DD + seg*8, ok ? 16 : 0);
        }
        for (int i = tid; i < 1024; i += 128) {
            int tile = i >> 9, idx = i & 511, row = idx >> 3, seg = idx & 7;
            uint32_t dst = smb + 16384 + tile*8192 + row*128 + ((seg*16) ^ ((row & 7) << 4));
            int krow = row;
            const __nv_bfloat16* base = tile ? g_kl : g_kh;
            cpasync16(dst, base + (kvbase + krow)*DD + seg*8, 16);
        }
        CP_COMMIT();
        loadV(0);
    }

    float sO[8][4];
#pragma unroll
    for (int nf = 0; nf < 8; nf++)
#pragma unroll
        for (int q = 0; q < 4; q++) sO[nf][q] = 0.f;
    float m0r = -1e30f, m1r = -1e30f, l0r = 0.f, l1r = 0.f;

    const int grow0 = q0 + w*16 + (l >> 2);
    const int grow1 = grow0 + 8;

    for (int kt = 0; kt <= qt; kt++) {
        const int k0 = kt << 6;
        CP_WAIT1();
        __syncthreads();

        float s[8][4];
#pragma unroll
        for (int nf = 0; nf < 8; nf++)
#pragma unroll
            for (int q = 0; q < 4; q++) s[nf][q] = 0.f;

#pragma unroll
        for (int kc = 0; kc < 4; kc++) {
            uint32_t aH[4], aL[4], bk[8][2];
            {
                int row = w*16 + (l & 15);
                int kb = kc*32 + ((l >> 4) << 4);
                uint32_t ad = smb + row*128 + (kb ^ ((row & 7) << 4));
                ldsm4(aH, ad);
                ldsm4(aL, ad + 8192);
            }
#pragma unroll
            for (int nj = 0; nj < 4; nj++) {
                int row = nj*16 + (l & 7) + ((l >> 4) << 3);
                int kb = kc*32 + (((l >> 3) & 1) << 4);
                uint32_t bd = smb + 16384 + row*128 + (kb ^ ((row & 7) << 4));
                uint32_t t[4];
                ldsm4(t, bd);
                bk[nj*2][0]=t[0]; bk[nj*2][1]=t[1]; bk[nj*2+1][0]=t[2]; bk[nj*2+1][1]=t[3];
            }
#pragma unroll
            for (int nf = 0; nf < 8; nf++) {
                mma16816(s[nf], aH, bk[nf]);
                mma16816(s[nf], aL, bk[nf]);
            }
#pragma unroll
            for (int nj = 0; nj < 4; nj++) {
                int row = nj*16 + (l & 7) + ((l >> 4) << 3);
                int kb = kc*32 + (((l >> 3) & 1) << 4);
                uint32_t bd = smb + 24576 + row*128 + (kb ^ ((row & 7) << 4));
                uint32_t t[4];
                ldsm4(t, bd);
                bk[nj*2][0]=t[0]; bk[nj*2][1]=t[1]; bk[nj*2+1][0]=t[2]; bk[nj*2+1][1]=t[3];
            }
#pragma unroll
            for (int nf = 0; nf < 8; nf++)
                mma16816(s[nf], aH, bk[nf]);
        }
        __syncthreads();
        if (kt < qt) loadK(k0 + 64);

        const bool diag = (kt == qt);
#pragma unroll
        for (int nf = 0; nf < 8; nf++) {
            int c0 = k0 + nf*8 + ((l & 3) << 1);
            s[nf][0] *= 0.125f; s[nf][1] *= 0.125f;
            s[nf][2] *= 0.125f; s[nf][3] *= 0.125f;
            if (diag) {
                if (c0     > grow0) s[nf][0] = -1e30f;
                if (c0 + 1 > grow0) s[nf][1] = -1e30f;
                if (c0     > grow1) s[nf][2] = -1e30f;
                if (c0 + 1 > grow1) s[nf][3] = -1e30f;
            }
        }

        float mx0 = -1e30f, mx1 = -1e30f;
#pragma unroll
        for (int nf = 0; nf < 8; nf++) {
            mx0 = fmaxf(mx0, fmaxf(s[nf][0], s[nf][1]));
            mx1 = fmaxf(mx1, fmaxf(s[nf][2], s[nf][3]));
        }
        mx0 = fmaxf(mx0, __shfl_xor_sync(0xffffffffu, mx0, 1));
        mx0 = fmaxf(mx0, __shfl_xor_sync(0xffffffffu, mx0, 2));
        mx1 = fmaxf(mx1, __shfl_xor_sync(0xffffffffu, mx1, 1));
        mx1 = fmaxf(mx1, __shfl_xor_sync(0xffffffffu, mx1, 2));
        float mn0 = fmaxf(m0r, mx0), mn1 = fmaxf(m1r, mx1);
        float al0 = __expf(m0r - mn0), al1 = __expf(m1r - mn1);
        m0r = mn0; m1r = mn1;

        float rs0 = 0.f, rs1 = 0.f;
#pragma unroll
        for (int nf = 0; nf < 8; nf++) {
            float p0 = __expf(s[nf][0] - mn0), p1 = __expf(s[nf][1] - mn0);
            float p2 = __expf(s[nf][2] - mn1), p3 = __expf(s[nf][3] - mn1);
            rs0 += p0 + p1; rs1 += p2 + p3;
            s[nf][0] = p0; s[nf][1] = p1; s[nf][2] = p2; s[nf][3] = p3;
        }
        rs0 += __shfl_xor_sync(0xffffffffu, rs0, 1);
        rs0 += __shfl_xor_sync(0xffffffffu, rs0, 2);
        rs1 += __shfl_xor_sync(0xffffffffu, rs1, 1);
        rs1 += __shfl_xor_sync(0xffffffffu, rs1, 2);
        l0r = l0r*al0 + rs0;
        l1r = l1r*al1 + rs1;

#pragma unroll
        for (int nf = 0; nf < 8; nf++) {
            sO[nf][0] *= al0; sO[nf][1] *= al0;
            sO[nf][2] *= al1; sO[nf][3] *= al1;
        }

        if (kt < qt) { CP_WAIT1(); } else { CP_WAIT0(); }
        __syncthreads();

#pragma unroll
        for (int kc = 0; kc < 4; kc++) {
            uint32_t pH[4], pL[4], bv[8][2];
            bfsplit2(s[2*kc][0],   s[2*kc][1],   pH[0], pL[0]);
            bfsplit2(s[2*kc][2],   s[2*kc][3],   pH[1], pL[1]);
            bfsplit2(s[2*kc+1][0], s[2*kc+1][1], pH[2], pL[2]);
            bfsplit2(s[2*kc+1][2], s[2*kc+1][3], pH[3], pL[3]);
#pragma unroll
            for (int i2 = 0; i2 < 4; i2++) {
                int row = kc*16 + (l & 7) + (((l >> 3) & 1) << 3);
                int cb = i2*32 + (((l >> 4) & 1) << 4);
                uint32_t vd = smb + 32768 + row*128 + (cb ^ ((row & 7) << 4));
                uint32_t t[4];
                ldsm4t(t, vd);
                bv[2*i2][0]=t[0]; bv[2*i2][1]=t[1]; bv[2*i2+1][0]=t[2]; bv[2*i2+1][1]=t[3];
            }
#pragma unroll
            for (int nf = 0; nf < 8; nf++) {
                mma16816(sO[nf], pH, bv[nf]);
                mma16816(sO[nf], pL, bv[nf]);
            }
#pragma unroll
            for (int i2 = 0; i2 < 4; i2++) {
                int row = kc*16 + (l & 7) + (((l >> 3) & 1) << 3);
                int cb = i2*32 + (((l >> 4) & 1) << 4);
                uint32_t vd = smb + 40960 + row*128 + (cb ^ ((row & 7) << 4));
                uint32_t t[4];
                ldsm4t(t, vd);
                bv[2*i2][0]=t[0]; bv[2*i2][1]=t[1]; bv[2*i2+1][0]=t[2]; bv[2*i2+1][1]=t[3];
            }
#pragma unroll
            for (int nf = 0; nf < 8; nf++)
                mma16816(sO[nf], pH, bv[nf]);
        }
        __syncthreads();
        if (kt < qt) loadV(k0 + 64);
    }

    float ascale = attn_scale[0];
    float inv0 = ascale / l0r, inv1 = ascale / l1r;
#pragma unroll
    for (int nf = 0; nf < 8; nf++) {
        int oc = h*DD + nf*8 + ((l & 3) << 1);
        if (grow0 >= NMETA && grow0 < TE) {
            float v0 = sO[nf][0]*inv0, v1 = sO[nf][1]*inv0;
            uint32_t hi, lo; bfsplit2(v0, v1, hi, lo);
            size_t base = ((size_t)(b*TT) + (grow0 - NMETA))*DIMM + oc;
            *(uint32_t*)&g_cath[base] = hi;
            *(uint32_t*)&g_catl[base] = lo;
        }
        if (grow1 >= NMETA && grow1 < TE) {
            float v2 = sO[nf][2]*inv1, v3 = sO[nf][3]*inv1;
            uint32_t hi, lo; bfsplit2(v2, v3, hi, lo);
            size_t base = ((size_t)(b*TT) + (grow1 - NMETA))*DIMM + oc;
            *(uint32_t*)&g_cath[base] = hi;
            *(uint32_t*)&g_catl[base] = lo;
        }
    }
}

// ================= SSM: dt / a / Bx / Cc =================
__global__ void dtbc_kernel(const float* __restrict__ dtw, const float* __restrict__ dtb,
                            const float* __restrict__ Bw,  const float* __restrict__ Cw,
                            const float* __restrict__ logA)
{
    __shared__ float xs[64][65];
    __shared__ float ws[48][65];
    __shared__ float dts[64][16];
    const int b = blockIdx.z, h = blockIdx.y, t0 = blockIdx.x*64;
    const int tid = threadIdx.x;

    for (int idx = tid; idx < 48*64; idx += 256) {
        int o = idx >> 6, k = idx & 63;
        float v;
        if (o < 16)      v = dtw[(h*16+o)*64 + k];
        else if (o < 32) v = Bw[(h*16+(o-16))*64 + k];
        else             v = Cw[(h*16+(o-32))*64 + k];
        ws[o][k] = v;
    }
    for (int idx = tid; idx < 64*64; idx += 256) {
        int r = idx >> 6, k = idx & 63;
        xs[r][k] = g_ssmx[((size_t)(b*TT)+t0+r)*(NSSM*DD) + h*DD + k];
    }
    __syncthreads();

    const int r = tid >> 2;
    const size_t obase = (((size_t)(b*NSSM+h))*TT + t0 + r)*SS;

    {
        int so = (tid & 3) << 2;
#pragma unroll
        for (int q = 0; q < 4; q++) {
            int o = so + q;
            float d = 0.f;
#pragma unroll
            for (int k = 0; k < 64; k++) d += xs[r][k]*ws[o][k];
            d += dtb[h*16 + o];
            float sp = (d > 20.f) ? d : log1pf(expf(d));
            float dt = fminf(sp, 1.0f);
            dts[r][o] = dt;
            float A  = fminf(-expf(logA[h*16 + o]), 10.0f);
            float la = fminf(fmaxf(dt*A, -0.5f), 0.0f);
            g_au[obase + o].x = expf(la);
        }
    }
    __syncthreads();
    {
        int jo = (tid & 3) << 3;
#pragma unroll
        for (int q = 0; q < 8; q++) {
            int o2 = jo + q;
            float d = 0.f;
#pragma unroll
            for (int k = 0; k < 64; k++) d += xs[r][k]*ws[16+o2][k];
            if (o2 < 16) g_au[obase + o2].y     = d * dts[r][o2];
            else         g_cc[obase + (o2-16)]  = d;
        }
    }
}

// ================= scan phase 1: local chunk scans (64 chunks x 32 steps) =================
// grid: 64 blocks = 16 bh x 4 chunk-groups; block 256 = 16 s x 16 chunks.
__global__ void scan1_kernel()
{
    const int bh = blockIdx.x >> 2, cg = blockIdx.x & 3;
    const int s = threadIdx.x & 15, ckl = threadIdx.x >> 4;
    const int chunk = cg*16 + ckl;
    const int t0 = chunk*SC_L;
    const size_t base = (size_t)bh*TT*SS + s;

    float hv = 0.f, p = 1.f;
#pragma unroll 4
    for (int t = 0; t < SC_L; t++) {
        size_t o = base + (size_t)(t0 + t)*SS;
        float2 au = g_au[o];
        p *= au.x;
        hv = fmaf(au.x, hv, au.y);
        g_hbuf[o] = hv;
        g_pp[o] = p;
    }
    g_carry[(bh*SS + s)*SC_C + chunk] = make_float2(hv, p);
}

// ================= scan phase 2: sequential carry scan per lane (256 lanes) =================
__global__ void scan2_kernel()
{
    int lane = blockIdx.x*64 + threadIdx.x;   // 4 blocks x 64
    if (lane >= BB*NSSM*SS) return;
    float hin = 0.f;
    const int cb = lane*SC_C;
#pragma unroll 4
    for (int c = 0; c < SC_C; c++) {
        g_hin[cb + c] = hin;
        float2 cr = g_carry[cb + c];
        hin = fmaf(cr.y, hin, cr.x);
    }
}

// ================= SSM epilogue (applies scan fixup on load) =================
__global__ void ssmout_kernel(const float* __restrict__ Ow, const float* __restrict__ ssm_scale)
{
    __shared__ float hs[64][17];
    __shared__ float cs[64][17];
    __shared__ float ows[64][17];
    const int b = blockIdx.z, h = blockIdx.y, t0 = blockIdx.x*64;
    const int tid = threadIdx.x;
    const int bh = b*NSSM + h;

    for (int idx = tid; idx < 64*16; idx += 256) {
        int r = idx >> 4, s = idx & 15;
        int t = t0 + r;
        size_t src = ((size_t)bh*TT + t)*SS + s;
        float hin = g_hin[(bh*SS + s)*SC_C + (t >> 5)];   // SC_L = 32
        hs[r][s] = fmaf(g_pp[src], hin, g_hbuf[src]);
        cs[r][s] = g_cc[src];
        ows[r][s] = Ow[(h*64 + r)*16 + s];
    }
    __syncthreads();

    const int r = tid >> 2, dp = tid & 3;
    float y = 0.f;
#pragma unroll
    for (int s = 0; s < 16; s++) y += cs[r][s]*hs[r][s];
    float x0 = g_ssmx[((size_t)(b*TT)+t0+r)*(NSSM*DD) + h*DD];
    float sc = ssm_scale[0];
    float yx = y * x0;
    size_t ob = ((size_t)(b*TT)+t0+r)*DIMM + 512 + h*DD + dp*16;
#pragma unroll
    for (int q = 0; q < 16; q++) {
        int d = dp*16 + q;
        float v = yx;
#pragma unroll
        for (int s = 0; s < 16; s++) v += hs[r][s]*ows[d][s];
        v *= sc;
        __nv_bfloat16 hh = __float2bfloat16(v);
        g_cath[ob + q] = hh;
        g_catl[ob + q] = __float2bfloat16(v - __bfloat162float(hh));
    }
}

// ================= launch =================
extern "C" void kernel_launch(void* const* d_in, const int* in_sizes, int n_in,
                              void* d_out, int out_size)
{
    const float* x         = (const float*)d_in[0];
    const float* meta      = (const float*)d_in[1];
    const float* qw        = (const float*)d_in[2];
    const float* kw        = (const float*)d_in[3];
    const float* vw        = (const float*)d_in[4];
    const float* qgain     = (const float*)d_in[5];
    const float* ssm_in_w  = (const float*)d_in[6];
    const float* projw     = (const float*)d_in[7];
    const float* attn_sc   = (const float*)d_in[8];
    const float* ssm_sc    = (const float*)d_in[9];
    const float* logA      = (const float*)d_in[10];
    const float* Bw        = (const float*)d_in[11];
    const float* Cw        = (const float*)d_in[12];
    const float* dtw       = (const float*)d_in[13];
    const float* dtb       = (const float*)d_in[14];
    const float* Ow        = (const float*)d_in[15];
    float* out = (float*)d_out;

    __nv_bfloat16 *p_xh, *p_xl, *p_wqh, *p_wql, *p_wsh, *p_wsl, *p_wph, *p_wpl, *p_cth, *p_ctl;
    float *p_qkv, *p_ssmx;
    cudaGetSymbolAddress((void**)&p_xh,  g_xh);
    cudaGetSymbolAddress((void**)&p_xl,  g_xl);
    cudaGetSymbolAddress((void**)&p_wqh, g_wqkvh);
    cudaGetSymbolAddress((void**)&p_wql, g_wqkvl);
    cudaGetSymbolAddress((void**)&p_wsh, g_wsh);
    cudaGetSymbolAddress((void**)&p_wsl, g_wsl);
    cudaGetSymbolAddress((void**)&p_wph, g_wph);
    cudaGetSymbolAddress((void**)&p_wpl, g_wpl);
    cudaGetSymbolAddress((void**)&p_cth, g_cath);
    cudaGetSymbolAddress((void**)&p_ctl, g_catl);
    cudaGetSymbolAddress((void**)&p_qkv,  g_qkv);
    cudaGetSymbolAddress((void**)&p_ssmx, g_ssmx);

    const int GEMM_SMEM = 2*32768;
    cudaFuncSetAttribute(gemm_mma_kernel, cudaFuncAttributeMaxDynamicSharedMemorySize, GEMM_SMEM);
    const int ATTN_SMEM = 6*8192;
    cudaFuncSetAttribute(attn_mma_kernel, cudaFuncAttributeMaxDynamicSharedMemorySize, ATTN_SMEM);

    const int CV_TOTAL = CV_XN + CV_W1 + CV_W2 + CV_W3;

    // single stream (multi-stream fork regressed under graph capture — reverted)
    conv_all_kernel<<<(CV_TOTAL + 255)/256, 256>>>(x, meta, qw, kw, vw, ssm_in_w, projw);
    gemm_mma_kernel<<<dim3(DIMM/128, (BB*TE + 127)/128), 256, GEMM_SMEM>>>(
        p_xh, p_xl, p_wqh, p_wql, p_qkv, BB*TE, DIMM, 0);
    {
        int warps = BB*(NATTN + NKV + NKV)*TE;
        normrot_kernel<<<(warps*32 + 255)/256, 256>>>(qgain);
    }
    attn_mma_kernel<<<dim3((TE + 63)/64, NATTN, BB), 128, ATTN_SMEM>>>(attn_sc);
    gemm_mma_kernel<<<dim3((NSSM*DD)/128, (BB*TT)/128), 256, GEMM_SMEM>>>(
        p_xh, p_xl, p_wsh, p_wsl, p_ssmx, BB*TT, NSSM*DD, 1);
    dtbc_kernel<<<dim3(TT/64, NSSM, BB), 256>>>(dtw, dtb, Bw, Cw, logA);
    scan1_kernel<<<64, 256>>>();
    scan2_kernel<<<4, 64>>>();
    ssmout_kernel<<<dim3(TT/64, NSSM, BB), 256>>>(Ow, ssm_sc);
    gemm_mma_kernel<<<dim3(DIMM/128, (BB*TT)/128), 256, GEMM_SMEM>>>(
        p_cth, p_ctl, p_wph, p_wpl, out, BB*TT, DIMM, 0);
}

// round 12
// speedup vs baseline: 1.4079x; 1.0492x over previous
#include <cuda_runtime.h>
#include <cuda_bf16.h>
#include <math.h>
#include <stdint.h>

#define BB     2
#define TT     2048
#define TE     2052
#define DIMM   1024
#define DD     64
#define NATTN  8
#define NKV    4
#define NSSM   8
#define SS     16
#define NMETA  4

// scan decomposition
#define SC_C   64
#define SC_L   32

// attention split-KV: chunks of <=8 kt-tiles; per (b,h): 85 chunks over qt=0..32
#define ACH_PER_BH 85
#define NQT 33

// ================= helpers =================
__device__ __forceinline__ uint32_t smem_u32(const void* p) {
    uint32_t a;
    asm("{ .reg .u64 t; cvta.to.shared.u64 t, %1; cvt.u32.u64 %0, t; }" : "=r"(a) : "l"(p));
    return a;
}
__device__ __forceinline__ void ldsm4(uint32_t* r, uint32_t addr) {
    asm volatile("ldmatrix.sync.aligned.m8n8.x4.shared.b16 {%0,%1,%2,%3}, [%4];"
        : "=r"(r[0]), "=r"(r[1]), "=r"(r[2]), "=r"(r[3]) : "r"(addr));
}
__device__ __forceinline__ void ldsm4t(uint32_t* r, uint32_t addr) {
    asm volatile("ldmatrix.sync.aligned.m8n8.x4.trans.shared.b16 {%0,%1,%2,%3}, [%4];"
        : "=r"(r[0]), "=r"(r[1]), "=r"(r[2]), "=r"(r[3]) : "r"(addr));
}
__device__ __forceinline__ void mma16816(float* c, const uint32_t* a, const uint32_t* b) {
    asm volatile("mma.sync.aligned.m16n8k16.row.col.f32.bf16.bf16.f32 "
        "{%0,%1,%2,%3}, {%4,%5,%6,%7}, {%8,%9}, {%0,%1,%2,%3};"
        : "+f"(c[0]), "+f"(c[1]), "+f"(c[2]), "+f"(c[3])
        : "r"(a[0]), "r"(a[1]), "r"(a[2]), "r"(a[3]), "r"(b[0]), "r"(b[1]));
}
__device__ __forceinline__ void cpasync16(uint32_t dst, const void* src, int srcsize) {
    asm volatile("cp.async.cg.shared.global [%0], [%1], 16, %2;"
        :: "r"(dst), "l"(src), "r"(srcsize) : "memory");
}
#define CP_COMMIT() asm volatile("cp.async.commit_group;" ::: "memory")
#define CP_WAIT0()  asm volatile("cp.async.wait_group 0;" ::: "memory")
#define CP_WAIT1()  asm volatile("cp.async.wait_group 1;" ::: "memory")
__device__ __forceinline__ void bfsplit2(float x, float y, uint32_t& hi, uint32_t& lo) {
    __nv_bfloat162 h2, l2;
    h2.x = __float2bfloat16(x); h2.y = __float2bfloat16(y);
    l2.x = __float2bfloat16(x - __bfloat162float(h2.x));
    l2.y = __float2bfloat16(y - __bfloat162float(h2.y));
    hi = *(uint32_t*)&h2; lo = *(uint32_t*)&l2;
}

// ================= scratch =================
__device__ __nv_bfloat16 g_xh[BB*TE*DIMM];
__device__ __nv_bfloat16 g_xl[BB*TE*DIMM];
__device__ __nv_bfloat16 g_wqkvh[DIMM*DIMM];
__device__ __nv_bfloat16 g_wqkvl[DIMM*DIMM];
__device__ __nv_bfloat16 g_wsh[NSSM*DD*DIMM];
__device__ __nv_bfloat16 g_wsl[NSSM*DD*DIMM];
__device__ __nv_bfloat16 g_wph[DIMM*DIMM];
__device__ __nv_bfloat16 g_wpl[DIMM*DIMM];
__device__ __nv_bfloat16 g_cath[BB*TT*DIMM];
__device__ __nv_bfloat16 g_catl[BB*TT*DIMM];
__device__ __nv_bfloat16 g_qh[BB*NATTN*TE*DD];
__device__ __nv_bfloat16 g_ql[BB*NATTN*TE*DD];
__device__ __nv_bfloat16 g_kh[BB*NKV*TE*DD];
__device__ __nv_bfloat16 g_kl[BB*NKV*TE*DD];
__device__ __nv_bfloat16 g_vh[BB*NKV*TE*DD];
__device__ __nv_bfloat16 g_vl[BB*NKV*TE*DD];
__device__ float  g_qkv [BB*TE*DIMM];
__device__ float  g_ssmx[BB*TT*NSSM*DD];
__device__ float2 g_au  [BB*NSSM*TT*SS];
__device__ float  g_cc  [BB*NSSM*TT*SS];
__device__ float  g_hbuf[BB*NSSM*TT*SS];
__device__ float  g_pp  [BB*NSSM*TT*SS];
__device__ float2 g_carry[BB*NSSM*SS*SC_C];
__device__ float  g_hin [BB*NSSM*SS*SC_C];
// attention split-KV partials: slot = ((b*NATTN+h)*NQT + qt)*5 + ci
__device__ float  g_pO [BB*NATTN*NQT*5*64*64];
__device__ float2 g_pml[BB*NATTN*NQT*5*64];

// chunk-id -> (qt, ci)
__device__ __forceinline__ void chunk_map(int c, int& qt, int& ci) {
    if (c < 8)       { qt = c;                ci = 0; }
    else if (c < 24) { qt = 8 + ((c-8) >> 1); ci = (c-8) & 1; }
    else if (c < 48) { qt = 16 + (c-24)/3;    ci = (c-24) % 3; }
    else if (c < 80) { qt = 24 + ((c-48)>>2); ci = (c-48) & 3; }
    else             { qt = 32;               ci = c - 80; }
}

// ================= fused conversion =================
#define CV_XN (BB*TE*DIMM)
#define CV_W1 (DIMM*DIMM)
#define CV_W2 (NSSM*DD*DIMM)
#define CV_W3 (DIMM*DIMM)
__global__ void conv_all_kernel(const float* __restrict__ x, const float* __restrict__ meta,
                                const float* __restrict__ qw, const float* __restrict__ kw,
                                const float* __restrict__ vw, const float* __restrict__ sw,
                                const float* __restrict__ pw)
{
    int idx = blockIdx.x*256 + threadIdx.x;
    float v; __nv_bfloat16 *dh, *dl; int off;
    if (idx < CV_XN) {
        int c = idx & 1023, row = idx >> 10;
        int b = row / TE, t = row % TE;
        v = (t < NMETA) ? meta[t*DIMM + c] : x[((size_t)(b*TT) + (t-NMETA))*DIMM + c];
        dh = g_xh; dl = g_xl; off = idx;
    } else if (idx < CV_XN + CV_W1) {
        int j = idx - CV_XN; int r = j >> 10, c = j & 1023;
        if (r < 512)      v = qw[r*DIMM + c];
        else if (r < 768) v = kw[(r-512)*DIMM + c];
        else              v = vw[(r-768)*DIMM + c];
        dh = g_wqkvh; dl = g_wqkvl; off = j;
    } else if (idx < CV_XN + CV_W1 + CV_W2) {
        int j = idx - CV_XN - CV_W1;
        v = sw[j]; dh = g_wsh; dl = g_wsl; off = j;
    } else if (idx < CV_XN + CV_W1 + CV_W2 + CV_W3) {
        int j = idx - CV_XN - CV_W1 - CV_W2;
        v = pw[j]; dh = g_wph; dl = g_wpl; off = j;
    } else return;
    __nv_bfloat16 h = __float2bfloat16(v);
    dh[off] = h;
    dl[off] = __float2bfloat16(v - __bfloat162float(h));
}

// ================= HMMA GEMM, 3xBF16 compensated, 2-stage pipelined =================
__global__ void __launch_bounds__(256, 2) gemm_mma_kernel(
    const __nv_bfloat16* __restrict__ Ah, const __nv_bfloat16* __restrict__ Al,
    const __nv_bfloat16* __restrict__ Bh, const __nv_bfloat16* __restrict__ Bl,
    float* __restrict__ C, int M, int N, int remap)
{
    extern __shared__ char smc[];
    const uint32_t smb = smem_u32(smc);
    const int tid = threadIdx.x, l = tid & 31, w = tid >> 5;
    const int wm = w & 3, wn = w >> 2;
    const int m0 = blockIdx.y << 7, n0 = blockIdx.x << 7;

    float acc[2][8][4];
#pragma unroll
    for (int mi = 0; mi < 2; mi++)
#pragma unroll
        for (int nf = 0; nf < 8; nf++)
#pragma unroll
            for (int q = 0; q < 4; q++) acc[mi][nf][q] = 0.f;

    auto fill = [&](int st, int c) {
        for (int i = tid; i < 2048; i += 256) {
            int tile = i >> 10, idx = i & 1023, row = idx >> 3, seg = idx & 7;
            uint32_t dst = smb + st*32768 + tile*16384 + row*128 + ((seg*16) ^ ((row & 7) << 4));
            const __nv_bfloat16* base;
            int grow, ok = 1;
            if (tile == 0) {
                grow = m0 + row;
                ok = grow < M;
                if (!ok) grow = 0;
                else if (remap) grow += 4*((grow >> 11) + 1);
                base = (seg < 4) ? Ah : Al;
            } else {
                grow = n0 + row;
                base = (seg < 4) ? Bh : Bl;
            }
            const void* src = base + ((size_t)grow << 10) + c*32 + (seg & 3)*8;
            cpasync16(dst, src, ok ? 16 : 0);
        }
        CP_COMMIT();
    };

    fill(0, 0);
    for (int c = 0; c < 32; c++) {
        const int st = c & 1;
        CP_WAIT0();
        __syncthreads();
        if (c + 1 < 32) fill(st ^ 1, c + 1);

        const uint32_t sA = smb + st*32768;
        const uint32_t sB = sA + 16384;
#pragma unroll
        for (int kk = 0; kk < 2; kk++) {
            uint32_t aH[2][4], aL[2][4], b[8][2];
#pragma unroll
            for (int mi = 0; mi < 2; mi++) {
                int row = wm*32 + mi*16 + (l & 15);
                int kb = kk*32 + ((l >> 4) << 4);
                uint32_t sw = (uint32_t)((row & 7) << 4);
                ldsm4(aH[mi], sA + row*128 + (kb ^ sw));
                ldsm4(aL[mi], sA + row*128 + ((kb + 64) ^ sw));
            }
#pragma unroll
            for (int nj = 0; nj < 4; nj++) {
                int row = wn*64 + nj*16 + (l & 7) + ((l >> 4) << 3);
                int kb = kk*32 + (((l >> 3) & 1) << 4);
                uint32_t t[4];
                ldsm4(t, sB + row*128 + (kb ^ ((row & 7) << 4)));
                b[nj*2][0]=t[0]; b[nj*2][1]=t[1]; b[nj*2+1][0]=t[2]; b[nj*2+1][1]=t[3];
            }
#pragma unroll
            for (int mi = 0; mi < 2; mi++)
#pragma unroll
                for (int nf = 0; nf < 8; nf++) {
                    mma16816(acc[mi][nf], aH[mi], b[nf]);
                    mma16816(acc[mi][nf], aL[mi], b[nf]);
                }
#pragma unroll
            for (int nj = 0; nj < 4; nj++) {
                int row = wn*64 + nj*16 + (l & 7) + ((l >> 4) << 3);
                int kb = kk*32 + (((l >> 3) & 1) << 4);
                uint32_t t[4];
                ldsm4(t, sB + row*128 + ((kb + 64) ^ ((row & 7) << 4)));
                b[nj*2][0]=t[0]; b[nj*2][1]=t[1]; b[nj*2+1][0]=t[2]; b[nj*2+1][1]=t[3];
            }
#pragma unroll
            for (int mi = 0; mi < 2; mi++)
#pragma unroll
                for (int nf = 0; nf < 8; nf++)
                    mma16816(acc[mi][nf], aH[mi], b[nf]);
        }
        __syncthreads();
    }

#pragma unroll
    for (int mi = 0; mi < 2; mi++) {
        int m = m0 + wm*32 + mi*16 + (l >> 2);
#pragma unroll
        for (int nf = 0; nf < 8; nf++) {
            int n = n0 + wn*64 + nf*8 + ((l & 3) << 1);
            if (m < M)
                *(float2*)&C[(size_t)m*N + n] = make_float2(acc[mi][nf][0], acc[mi][nf][1]);
            if (m + 8 < M)
                *(float2*)&C[(size_t)(m+8)*N + n] = make_float2(acc[mi][nf][2], acc[mi][nf][3]);
        }
    }
}

// ================= RMSNorm + RoPE (+q_gain) -> bf16 hi/lo; V convert =================
__global__ void normrot_kernel(const float* __restrict__ qgain)
{
    const int QROWS = BB*NATTN*TE;
    const int KROWS = BB*NKV*TE;
    const int VROWS = BB*NKV*TE;
    int gw = (blockIdx.x*blockDim.x + threadIdx.x) >> 5;
    int lane = threadIdx.x & 31;
    if (gw >= QROWS + KROWS + VROWS) return;

    if (gw < QROWS + KROWS) {
        const float* src; __nv_bfloat16 *dh, *dl; size_t doff; float gain; int t;
        if (gw < QROWS) {
            int b = gw / (NATTN*TE); int r = gw % (NATTN*TE); int h = r / TE; t = r % TE;
            src = &g_qkv[((size_t)(b*TE)+t)*DIMM + h*DD];
            doff = (((size_t)(b*NATTN+h))*TE + t)*DD;
            dh = g_qh; dl = g_ql;
            gain = qgain[h];
        } else {
            int w2 = gw - QROWS;
            int b = w2 / (NKV*TE); int r = w2 % (NKV*TE); int h = r / TE; t = r % TE;
            src = &g_qkv[((size_t)(b*TE)+t)*DIMM + 512 + h*DD];
            doff = (((size_t)(b*NKV+h))*TE + t)*DD;
            dh = g_kh; dl = g_kl;
            gain = 1.0f;
        }
        float x1 = src[lane], x2 = src[lane+32];
        float ss = x1*x1 + x2*x2;
#pragma unroll
        for (int o = 16; o > 0; o >>= 1) ss += __shfl_xor_sync(0xffffffffu, ss, o);
        float rinv = rsqrtf(ss*(1.0f/64.0f) + 1e-6f);
        x1 *= rinv; x2 *= rinv;
        float inv = expf(-(float)lane * 0.28782313662425575f);
        float f = (float)t * inv;
        float sn, cs; sincosf(f, &sn, &cs);
        float y1 = (x1*cs - x2*sn) * gain;
        float y2 = (x1*sn + x2*cs) * gain;
        __nv_bfloat16 h1 = __float2bfloat16(y1), h2 = __float2bfloat16(y2);
        dh[doff + lane]      = h1;
        dh[doff + lane + 32] = h2;
        dl[doff + lane]      = __float2bfloat16(y1 - __bfloat162float(h1));
        dl[doff + lane + 32] = __float2bfloat16(y2 - __bfloat162float(h2));
    } else {
        int w2 = gw - QROWS - KROWS;
        int b = w2 / (NKV*TE); int r = w2 % (NKV*TE); int h = r / TE; int t = r % TE;
        const float* src = &g_qkv[((size_t)(b*TE)+t)*DIMM + 768 + h*DD];
        size_t doff = (((size_t)(b*NKV+h))*TE + t)*DD;
        float v1 = src[lane], v2 = src[lane+32];
        __nv_bfloat16 h1 = __float2bfloat16(v1), h2 = __float2bfloat16(v2);
        g_vh[doff + lane]      = h1;
        g_vh[doff + lane + 32] = h2;
        g_vl[doff + lane]      = __float2bfloat16(v1 - __bfloat162float(h1));
        g_vl[doff + lane + 32] = __float2bfloat16(v2 - __bfloat162float(h2));
    }
}

// ================= HMMA flash attention, split-KV chunks =================
__global__ void __launch_bounds__(128) attn_mma_kernel(const float* __restrict__ attn_scale)
{
    extern __shared__ char smc[];
    const uint32_t smb = smem_u32(smc);
    const int b = blockIdx.z, h = blockIdx.y;
    int qt, ci;
    chunk_map(ACH_PER_BH - 1 - (int)blockIdx.x, qt, ci);   // heavy chunks first
    const int nch = (qt >> 3) + 1;
    const int q0 = qt << 6;
    const int kt_begin = ci << 3;
    const int kt_end = min(kt_begin + 8, qt + 1);
    const int hkv = h >> 1;
    const int tid = threadIdx.x, l = tid & 31, w = tid >> 5;

    const size_t qbase = ((size_t)(b*NATTN+h))*TE;
    const size_t kvbase = ((size_t)(b*NKV+hkv))*TE;

    auto loadK = [&](int k0) {
        for (int i = tid; i < 1024; i += 128) {
            int tile = i >> 9, idx = i & 511, row = idx >> 3, seg = idx & 7;
            uint32_t dst = smb + 16384 + tile*8192 + row*128 + ((seg*16) ^ ((row & 7) << 4));
            int krow = k0 + row;
            int ok = krow < TE;
            const __nv_bfloat16* base = tile ? g_kl : g_kh;
            cpasync16(dst, base + (kvbase + (ok ? krow : 0))*DD + seg*8, ok ? 16 : 0);
        }
        CP_COMMIT();
    };
    auto loadV = [&](int k0) {
        for (int i = tid; i < 1024; i += 128) {
            int tile = i >> 9, idx = i & 511, row = idx >> 3, seg = idx & 7;
            uint32_t dst = smb + 32768 + tile*8192 + row*128 + ((seg*16) ^ ((row & 7) << 4));
            int krow = k0 + row;
            int ok = krow < TE;
            const __nv_bfloat16* base = tile ? g_vl : g_vh;
            cpasync16(dst, base + (kvbase + (ok ? krow : 0))*DD + seg*8, ok ? 16 : 0);
        }
        CP_COMMIT();
    };

    {   // prologue: {Q, K(kt_begin)}, {V(kt_begin)}
        for (int i = tid; i < 1024; i += 128) {
            int tile = i >> 9, idx = i & 511, row = idx >> 3, seg = idx & 7;
            uint32_t dst = smb + tile*8192 + row*128 + ((seg*16) ^ ((row & 7) << 4));
            int qrow = q0 + row;
            int ok = qrow < TE;
            const __nv_bfloat16* base = tile ? g_ql : g_qh;
            cpasync16(dst, base + (qbase + (ok ? qrow : 0))*DD + seg*8, ok ? 16 : 0);
        }
        for (int i = tid; i < 1024; i += 128) {
            int tile = i >> 9, idx = i & 511, row = idx >> 3, seg = idx & 7;
            uint32_t dst = smb + 16384 + tile*8192 + row*128 + ((seg*16) ^ ((row & 7) << 4));
            int krow = (kt_begin << 6) + row;
            int ok = krow < TE;
            const __nv_bfloat16* base = tile ? g_kl : g_kh;
            cpasync16(dst, base + (kvbase + (ok ? krow : 0))*DD + seg*8, ok ? 16 : 0);
        }
        CP_COMMIT();
        loadV(kt_begin << 6);
    }

    float sO[8][4];
#pragma unroll
    for (int nf = 0; nf < 8; nf++)
#pragma unroll
        for (int q = 0; q < 4; q++) sO[nf][q] = 0.f;
    float m0r = -1e30f, m1r = -1e30f, l0r = 0.f, l1r = 0.f;

    const int grow0 = q0 + w*16 + (l >> 2);
    const int grow1 = grow0 + 8;

    for (int kt = kt_begin; kt < kt_end; kt++) {
        const int k0 = kt << 6;
        CP_WAIT1();
        __syncthreads();

        float s[8][4];
#pragma unroll
        for (int nf = 0; nf < 8; nf++)
#pragma unroll
            for (int q = 0; q < 4; q++) s[nf][q] = 0.f;

#pragma unroll
        for (int kc = 0; kc < 4; kc++) {
            uint32_t aH[4], aL[4], bk[8][2];
            {
                int row = w*16 + (l & 15);
                int kb = kc*32 + ((l >> 4) << 4);
                uint32_t ad = smb + row*128 + (kb ^ ((row & 7) << 4));
                ldsm4(aH, ad);
                ldsm4(aL, ad + 8192);
            }
#pragma unroll
            for (int nj = 0; nj < 4; nj++) {
                int row = nj*16 + (l & 7) + ((l >> 4) << 3);
                int kb = kc*32 + (((l >> 3) & 1) << 4);
                uint32_t bd = smb + 16384 + row*128 + (kb ^ ((row & 7) << 4));
                uint32_t t[4];
                ldsm4(t, bd);
                bk[nj*2][0]=t[0]; bk[nj*2][1]=t[1]; bk[nj*2+1][0]=t[2]; bk[nj*2+1][1]=t[3];
            }
#pragma unroll
            for (int nf = 0; nf < 8; nf++) {
                mma16816(s[nf], aH, bk[nf]);
                mma16816(s[nf], aL, bk[nf]);
            }
#pragma unroll
            for (int nj = 0; nj < 4; nj++) {
                int row = nj*16 + (l & 7) + ((l >> 4) << 3);
                int kb = kc*32 + (((l >> 3) & 1) << 4);
                uint32_t bd = smb + 24576 + row*128 + (kb ^ ((row & 7) << 4));
                uint32_t t[4];
                ldsm4(t, bd);
                bk[nj*2][0]=t[0]; bk[nj*2][1]=t[1]; bk[nj*2+1][0]=t[2]; bk[nj*2+1][1]=t[3];
            }
#pragma unroll
            for (int nf = 0; nf < 8; nf++)
                mma16816(s[nf], aH, bk[nf]);
        }
        __syncthreads();
        if (kt + 1 < kt_end) loadK((kt + 1) << 6);

        const bool diag = (kt == qt);
#pragma unroll
        for (int nf = 0; nf < 8; nf++) {
            int c0 = k0 + nf*8 + ((l & 3) << 1);
            s[nf][0] *= 0.125f; s[nf][1] *= 0.125f;
            s[nf][2] *= 0.125f; s[nf][3] *= 0.125f;
            if (diag) {
                if (c0     > grow0) s[nf][0] = -1e30f;
                if (c0 + 1 > grow0) s[nf][1] = -1e30f;
                if (c0     > grow1) s[nf][2] = -1e30f;
                if (c0 + 1 > grow1) s[nf][3] = -1e30f;
            }
        }

        float mx0 = -1e30f, mx1 = -1e30f;
#pragma unroll
        for (int nf = 0; nf < 8; nf++) {
            mx0 = fmaxf(mx0, fmaxf(s[nf][0], s[nf][1]));
            mx1 = fmaxf(mx1, fmaxf(s[nf][2], s[nf][3]));
        }
        mx0 = fmaxf(mx0, __shfl_xor_sync(0xffffffffu, mx0, 1));
        mx0 = fmaxf(mx0, __shfl_xor_sync(0xffffffffu, mx0, 2));
        mx1 = fmaxf(mx1, __shfl_xor_sync(0xffffffffu, mx1, 1));
        mx1 = fmaxf(mx1, __shfl_xor_sync(0xffffffffu, mx1, 2));
        float mn0 = fmaxf(m0r, mx0), mn1 = fmaxf(m1r, mx1);
        float al0 = __expf(m0r - mn0), al1 = __expf(m1r - mn1);
        m0r = mn0; m1r = mn1;

        float rs0 = 0.f, rs1 = 0.f;
#pragma unroll
        for (int nf = 0; nf < 8; nf++) {
            float p0 = __expf(s[nf][0] - mn0), p1 = __expf(s[nf][1] - mn0);
            float p2 = __expf(s[nf][2] - mn1), p3 = __expf(s[nf][3] - mn1);
            rs0 += p0 + p1; rs1 += p2 + p3;
            s[nf][0] = p0; s[nf][1] = p1; s[nf][2] = p2; s[nf][3] = p3;
        }
        rs0 += __shfl_xor_sync(0xffffffffu, rs0, 1);
        rs0 += __shfl_xor_sync(0xffffffffu, rs0, 2);
        rs1 += __shfl_xor_sync(0xffffffffu, rs1, 1);
        rs1 += __shfl_xor_sync(0xffffffffu, rs1, 2);
        l0r = l0r*al0 + rs0;
        l1r = l1r*al1 + rs1;

#pragma unroll
        for (int nf = 0; nf < 8; nf++) {
            sO[nf][0] *= al0; sO[nf][1] *= al0;
            sO[nf][2] *= al1; sO[nf][3] *= al1;
        }

        if (kt + 1 < kt_end) { CP_WAIT1(); } else { CP_WAIT0(); }
        __syncthreads();

#pragma unroll
        for (int kc = 0; kc < 4; kc++) {
            uint32_t pH[4], pL[4], bv[8][2];
            bfsplit2(s[2*kc][0],   s[2*kc][1],   pH[0], pL[0]);
            bfsplit2(s[2*kc][2],   s[2*kc][3],   pH[1], pL[1]);
            bfsplit2(s[2*kc+1][0], s[2*kc+1][1], pH[2], pL[2]);
            bfsplit2(s[2*kc+1][2], s[2*kc+1][3], pH[3], pL[3]);
#pragma unroll
            for (int i2 = 0; i2 < 4; i2++) {
                int row = kc*16 + (l & 7) + (((l >> 3) & 1) << 3);
                int cb = i2*32 + (((l >> 4) & 1) << 4);
                uint32_t vd = smb + 32768 + row*128 + (cb ^ ((row & 7) << 4));
                uint32_t t[4];
                ldsm4t(t, vd);
                bv[2*i2][0]=t[0]; bv[2*i2][1]=t[1]; bv[2*i2+1][0]=t[2]; bv[2*i2+1][1]=t[3];
            }
#pragma unroll
            for (int nf = 0; nf < 8; nf++) {
                mma16816(sO[nf], pH, bv[nf]);
                mma16816(sO[nf], pL, bv[nf]);
            }
#pragma unroll
            for (int i2 = 0; i2 < 4; i2++) {
                int row = kc*16 + (l & 7) + (((l >> 3) & 1) << 3);
                int cb = i2*32 + (((l >> 4) & 1) << 4);
                uint32_t vd = smb + 40960 + row*128 + (cb ^ ((row & 7) << 4));
                uint32_t t[4];
                ldsm4t(t, vd);
                bv[2*i2][0]=t[0]; bv[2*i2][1]=t[1]; bv[2*i2+1][0]=t[2]; bv[2*i2+1][1]=t[3];
            }
#pragma unroll
            for (int nf = 0; nf < 8; nf++)
                mma16816(sO[nf], pH, bv[nf]);
        }
        __syncthreads();
        if (kt + 1 < kt_end) loadV((kt + 1) << 6);
    }

    if (nch == 1) {
        // direct finalize
        float ascale = attn_scale[0];
        float inv0 = ascale / l0r, inv1 = ascale / l1r;
#pragma unroll
        for (int nf = 0; nf < 8; nf++) {
            int oc = h*DD + nf*8 + ((l & 3) << 1);
            if (grow0 >= NMETA && grow0 < TE) {
                float v0 = sO[nf][0]*inv0, v1 = sO[nf][1]*inv0;
                uint32_t hi, lo; bfsplit2(v0, v1, hi, lo);
                size_t base = ((size_t)(b*TT) + (grow0 - NMETA))*DIMM + oc;
                *(uint32_t*)&g_cath[base] = hi;
                *(uint32_t*)&g_catl[base] = lo;
            }
            if (grow1 >= NMETA && grow1 < TE) {
                float v2 = sO[nf][2]*inv1, v3 = sO[nf][3]*inv1;
                uint32_t hi, lo; bfsplit2(v2, v3, hi, lo);
                size_t base = ((size_t)(b*TT) + (grow1 - NMETA))*DIMM + oc;
                *(uint32_t*)&g_cath[base] = hi;
                *(uint32_t*)&g_catl[base] = lo;
            }
        }
    } else {
        // write partial (unnormalized O, m, l)
        const int slot = (((b*NATTN+h)*NQT) + qt)*5 + ci;
        float* po = g_pO + (size_t)slot*4096;
        const int r0 = w*16 + (l >> 2), r1 = r0 + 8;
#pragma unroll
        for (int nf = 0; nf < 8; nf++) {
            int ccol = nf*8 + ((l & 3) << 1);
            *(float2*)&po[r0*64 + ccol] = make_float2(sO[nf][0], sO[nf][1]);
            *(float2*)&po[r1*64 + ccol] = make_float2(sO[nf][2], sO[nf][3]);
        }
        if ((l & 3) == 0) {
            g_pml[(size_t)slot*64 + r0] = make_float2(m0r, l0r);
            g_pml[(size_t)slot*64 + r1] = make_float2(m1r, l1r);
        }
    }
}

// ================= attention merge (tiles with qt >= 8) =================
__global__ void __launch_bounds__(256) attn_merge_kernel(const float* __restrict__ attn_scale)
{
    const int b = blockIdx.z, h = blockIdx.y;
    const int qt = 8 + (int)blockIdx.x;
    const int nch = (qt >> 3) + 1;
    const int tid = threadIdx.x;
    const int r = tid >> 2, cg = (tid & 3) << 4;        // row 0..63, 16-col group
    const int slot0 = (((b*NATTN+h)*NQT) + qt)*5;

    float mi[5], li[5];
    float mstar = -1e30f;
    for (int ci = 0; ci < nch; ci++) {
        float2 ml = g_pml[(size_t)(slot0+ci)*64 + r];
        mi[ci] = ml.x; li[ci] = ml.y;
        mstar = fmaxf(mstar, ml.x);
    }
    float L = 0.f;
    float wf[5];
    for (int ci = 0; ci < nch; ci++) {
        wf[ci] = __expf(mi[ci] - mstar);
        L += wf[ci]*li[ci];
    }
    float acc[16];
#pragma unroll
    for (int j = 0; j < 16; j++) acc[j] = 0.f;
    for (int ci = 0; ci < nch; ci++) {
        const float* po = g_pO + (size_t)(slot0+ci)*4096 + r*64 + cg;
        float wfc = wf[ci];
#pragma unroll
        for (int j = 0; j < 16; j += 4) {
            float4 v = *(const float4*)&po[j];
            acc[j]   += wfc*v.x; acc[j+1] += wfc*v.y;
            acc[j+2] += wfc*v.z; acc[j+3] += wfc*v.w;
        }
    }
    int q = (qt << 6) + r;
    if (q >= NMETA && q < TE) {
        float sc = attn_scale[0] / L;
        size_t base = ((size_t)(b*TT) + (q - NMETA))*DIMM + h*DD + cg;
#pragma unroll
        for (int j = 0; j < 16; j += 2) {
            uint32_t hi, lo;
            bfsplit2(acc[j]*sc, acc[j+1]*sc, hi, lo);
            *(uint32_t*)&g_cath[base + j] = hi;
            *(uint32_t*)&g_catl[base + j] = lo;
        }
    }
}

// ================= SSM: dt / a / Bx / Cc =================
__global__ void dtbc_kernel(const float* __restrict__ dtw, const float* __restrict__ dtb,
                            const float* __restrict__ Bw,  const float* __restrict__ Cw,
                            const float* __restrict__ logA)
{
    __shared__ float xs[64][65];
    __shared__ float ws[48][65];
    __shared__ float dts[64][16];
    const int b = blockIdx.z, h = blockIdx.y, t0 = blockIdx.x*64;
    const int tid = threadIdx.x;

    for (int idx = tid; idx < 48*64; idx += 256) {
        int o = idx >> 6, k = idx & 63;
        float v;
        if (o < 16)      v = dtw[(h*16+o)*64 + k];
        else if (o < 32) v = Bw[(h*16+(o-16))*64 + k];
        else             v = Cw[(h*16+(o-32))*64 + k];
        ws[o][k] = v;
    }
    for (int idx = tid; idx < 64*64; idx += 256) {
        int r = idx >> 6, k = idx & 63;
        xs[r][k] = g_ssmx[((size_t)(b*TT)+t0+r)*(NSSM*DD) + h*DD + k];
    }
    __syncthreads();

    const int r = tid >> 2;
    const size_t obase = (((size_t)(b*NSSM+h))*TT + t0 + r)*SS;

    {
        int so = (tid & 3) << 2;
#pragma unroll
        for (int q = 0; q < 4; q++) {
            int o = so + q;
            float d = 0.f;
#pragma unroll
            for (int k = 0; k < 64; k++) d += xs[r][k]*ws[o][k];
            d += dtb[h*16 + o];
            float sp = (d > 20.f) ? d : log1pf(expf(d));
            float dt = fminf(sp, 1.0f);
            dts[r][o] = dt;
            float A  = fminf(-expf(logA[h*16 + o]), 10.0f);
            float la = fminf(fmaxf(dt*A, -0.5f), 0.0f);
            g_au[obase + o].x = expf(la);
        }
    }
    __syncthreads();
    {
        int jo = (tid & 3) << 3;
#pragma unroll
        for (int q = 0; q < 8; q++) {
            int o2 = jo + q;
            float d = 0.f;
#pragma unroll
            for (int k = 0; k < 64; k++) d += xs[r][k]*ws[16+o2][k];
            if (o2 < 16) g_au[obase + o2].y     = d * dts[r][o2];
            else         g_cc[obase + (o2-16)]  = d;
        }
    }
}

// ================= scan phase 1 =================
__global__ void scan1_kernel()
{
    const int bh = blockIdx.x >> 2, cg = blockIdx.x & 3;
    const int s = threadIdx.x & 15, ckl = threadIdx.x >> 4;
    const int chunk = cg*16 + ckl;
    const int t0 = chunk*SC_L;
    const size_t base = (size_t)bh*TT*SS + s;

    float hv = 0.f, p = 1.f;
#pragma unroll 4
    for (int t = 0; t < SC_L; t++) {
        size_t o = base + (size_t)(t0 + t)*SS;
        float2 au = g_au[o];
        p *= au.x;
        hv = fmaf(au.x, hv, au.y);
        g_hbuf[o] = hv;
        g_pp[o] = p;
    }
    g_carry[(bh*SS + s)*SC_C + chunk] = make_float2(hv, p);
}

// ================= scan phase 2 =================
__global__ void scan2_kernel()
{
    int lane = blockIdx.x*64 + threadIdx.x;
    if (lane >= BB*NSSM*SS) return;
    float hin = 0.f;
    const int cb = lane*SC_C;
#pragma unroll 4
    for (int c = 0; c < SC_C; c++) {
        g_hin[cb + c] = hin;
        float2 cr = g_carry[cb + c];
        hin = fmaf(cr.y, hin, cr.x);
    }
}

// ================= SSM epilogue =================
__global__ void ssmout_kernel(const float* __restrict__ Ow, const float* __restrict__ ssm_scale)
{
    __shared__ float hs[64][17];
    __shared__ float cs[64][17];
    __shared__ float ows[64][17];
    const int b = blockIdx.z, h = blockIdx.y, t0 = blockIdx.x*64;
    const int tid = threadIdx.x;
    const int bh = b*NSSM + h;

    for (int idx = tid; idx < 64*16; idx += 256) {
        int r = idx >> 4, s = idx & 15;
        int t = t0 + r;
        size_t src = ((size_t)bh*TT + t)*SS + s;
        float hin = g_hin[(bh*SS + s)*SC_C + (t >> 5)];
        hs[r][s] = fmaf(g_pp[src], hin, g_hbuf[src]);
        cs[r][s] = g_cc[src];
        ows[r][s] = Ow[(h*64 + r)*16 + s];
    }
    __syncthreads();

    const int r = tid >> 2, dp = tid & 3;
    float y = 0.f;
#pragma unroll
    for (int s = 0; s < 16; s++) y += cs[r][s]*hs[r][s];
    float x0 = g_ssmx[((size_t)(b*TT)+t0+r)*(NSSM*DD) + h*DD];
    float sc = ssm_scale[0];
    float yx = y * x0;
    size_t ob = ((size_t)(b*TT)+t0+r)*DIMM + 512 + h*DD + dp*16;
#pragma unroll
    for (int q = 0; q < 16; q++) {
        int d = dp*16 + q;
        float v = yx;
#pragma unroll
        for (int s = 0; s < 16; s++) v += hs[r][s]*ows[d][s];
        v *= sc;
        __nv_bfloat16 hh = __float2bfloat16(v);
        g_cath[ob + q] = hh;
        g_catl[ob + q] = __float2bfloat16(v - __bfloat162float(hh));
    }
}

// ================= launch =================
extern "C" void kernel_launch(void* const* d_in, const int* in_sizes, int n_in,
                              void* d_out, int out_size)
{
    const float* x         = (const float*)d_in[0];
    const float* meta      = (const float*)d_in[1];
    const float* qw        = (const float*)d_in[2];
    const float* kw        = (const float*)d_in[3];
    const float* vw        = (const float*)d_in[4];
    const float* qgain     = (const float*)d_in[5];
    const float* ssm_in_w  = (const float*)d_in[6];
    const float* projw     = (const float*)d_in[7];
    const float* attn_sc   = (const float*)d_in[8];
    const float* ssm_sc    = (const float*)d_in[9];
    const float* logA      = (const float*)d_in[10];
    const float* Bw        = (const float*)d_in[11];
    const float* Cw        = (const float*)d_in[12];
    const float* dtw       = (const float*)d_in[13];
    const float* dtb       = (const float*)d_in[14];
    const float* Ow        = (const float*)d_in[15];
    float* out = (float*)d_out;

    __nv_bfloat16 *p_xh, *p_xl, *p_wqh, *p_wql, *p_wsh, *p_wsl, *p_wph, *p_wpl, *p_cth, *p_ctl;
    float *p_qkv, *p_ssmx;
    cudaGetSymbolAddress((void**)&p_xh,  g_xh);
    cudaGetSymbolAddress((void**)&p_xl,  g_xl);
    cudaGetSymbolAddress((void**)&p_wqh, g_wqkvh);
    cudaGetSymbolAddress((void**)&p_wql, g_wqkvl);
    cudaGetSymbolAddress((void**)&p_wsh, g_wsh);
    cudaGetSymbolAddress((void**)&p_wsl, g_wsl);
    cudaGetSymbolAddress((void**)&p_wph, g_wph);
    cudaGetSymbolAddress((void**)&p_wpl, g_wpl);
    cudaGetSymbolAddress((void**)&p_cth, g_cath);
    cudaGetSymbolAddress((void**)&p_ctl, g_catl);
    cudaGetSymbolAddress((void**)&p_qkv,  g_qkv);
    cudaGetSymbolAddress((void**)&p_ssmx, g_ssmx);

    const int GEMM_SMEM = 2*32768;
    cudaFuncSetAttribute(gemm_mma_kernel, cudaFuncAttributeMaxDynamicSharedMemorySize, GEMM_SMEM);
    const int ATTN_SMEM = 6*8192;
    cudaFuncSetAttribute(attn_mma_kernel, cudaFuncAttributeMaxDynamicSharedMemorySize, ATTN_SMEM);

    const int CV_TOTAL = CV_XN + CV_W1 + CV_W2 + CV_W3;

    conv_all_kernel<<<(CV_TOTAL + 255)/256, 256>>>(x, meta, qw, kw, vw, ssm_in_w, projw);
    gemm_mma_kernel<<<dim3(DIMM/128, (BB*TE + 127)/128), 256, GEMM_SMEM>>>(
        p_xh, p_xl, p_wqh, p_wql, p_qkv, BB*TE, DIMM, 0);
    {
        int warps = BB*(NATTN + NKV + NKV)*TE;
        normrot_kernel<<<(warps*32 + 255)/256, 256>>>(qgain);
    }
    attn_mma_kernel<<<dim3(ACH_PER_BH, NATTN, BB), 128, ATTN_SMEM>>>(attn_sc);
    attn_merge_kernel<<<dim3(NQT - 8, NATTN, BB), 256>>>(attn_sc);
    gemm_mma_kernel<<<dim3((NSSM*DD)/128, (BB*TT)/128), 256, GEMM_SMEM>>>(
        p_xh, p_xl, p_wsh, p_wsl, p_ssmx, BB*TT, NSSM*DD, 1);
    dtbc_kernel<<<dim3(TT/64, NSSM, BB), 256>>>(dtw, dtb, Bw, Cw, logA);
    scan1_kernel<<<64, 256>>>();
    scan2_kernel<<<4, 64>>>();
    ssmout_kernel<<<dim3(TT/64, NSSM, BB), 256>>>(Ow, ssm_sc);
    gemm_mma_kernel<<<dim3(DIMM/128, (BB*TT)/128), 256, GEMM_SMEM>>>(
        p_cth, p_ctl, p_wph, p_wpl, out, BB*TT, DIMM, 0);
}

// round 14
// speedup vs baseline: 1.6760x; 1.1905x over previous
#include <cuda_runtime.h>
#include <cuda_bf16.h>
#include <cuda_fp16.h>
#include <math.h>
#include <stdint.h>

#define BB     2
#define TT     2048
#define TE     2052
#define DIMM   1024
#define DD     64
#define NATTN  8
#define NKV    4
#define NSSM   8
#define SS     16
#define NMETA  4

#define SC_C   64
#define SC_L   32
#define ACH_PER_BH 85
#define NQT 33

// ================= helpers =================
__device__ __forceinline__ uint32_t smem_u32(const void* p) {
    uint32_t a;
    asm("{ .reg .u64 t; cvta.to.shared.u64 t, %1; cvt.u32.u64 %0, t; }" : "=r"(a) : "l"(p));
    return a;
}
__device__ __forceinline__ void ldsm4(uint32_t* r, uint32_t addr) {
    asm volatile("ldmatrix.sync.aligned.m8n8.x4.shared.b16 {%0,%1,%2,%3}, [%4];"
        : "=r"(r[0]), "=r"(r[1]), "=r"(r[2]), "=r"(r[3]) : "r"(addr));
}
__device__ __forceinline__ void ldsm4t(uint32_t* r, uint32_t addr) {
    asm volatile("ldmatrix.sync.aligned.m8n8.x4.trans.shared.b16 {%0,%1,%2,%3}, [%4];"
        : "=r"(r[0]), "=r"(r[1]), "=r"(r[2]), "=r"(r[3]) : "r"(addr));
}
__device__ __forceinline__ void mma16816(float* c, const uint32_t* a, const uint32_t* b) {
    asm volatile("mma.sync.aligned.m16n8k16.row.col.f32.bf16.bf16.f32 "
        "{%0,%1,%2,%3}, {%4,%5,%6,%7}, {%8,%9}, {%0,%1,%2,%3};"
        : "+f"(c[0]), "+f"(c[1]), "+f"(c[2]), "+f"(c[3])
        : "r"(a[0]), "r"(a[1]), "r"(a[2]), "r"(a[3]), "r"(b[0]), "r"(b[1]));
}
__device__ __forceinline__ void mma16816h(float* c, const uint32_t* a, const uint32_t* b) {
    asm volatile("mma.sync.aligned.m16n8k16.row.col.f32.f16.f16.f32 "
        "{%0,%1,%2,%3}, {%4,%5,%6,%7}, {%8,%9}, {%0,%1,%2,%3};"
        : "+f"(c[0]), "+f"(c[1]), "+f"(c[2]), "+f"(c[3])
        : "r"(a[0]), "r"(a[1]), "r"(a[2]), "r"(a[3]), "r"(b[0]), "r"(b[1]));
}
__device__ __forceinline__ void cpasync16(uint32_t dst, const void* src, int srcsize) {
    asm volatile("cp.async.cg.shared.global [%0], [%1], 16, %2;"
        :: "r"(dst), "l"(src), "r"(srcsize) : "memory");
}
#define CP_COMMIT() asm volatile("cp.async.commit_group;" ::: "memory")
#define CP_WAIT0()  asm volatile("cp.async.wait_group 0;" ::: "memory")
#define CP_WAIT1()  asm volatile("cp.async.wait_group 1;" ::: "memory")
__device__ __forceinline__ void bfsplit2(float x, float y, uint32_t& hi, uint32_t& lo) {
    __nv_bfloat162 h2, l2;
    h2.x = __float2bfloat16(x); h2.y = __float2bfloat16(y);
    l2.x = __float2bfloat16(x - __bfloat162float(h2.x));
    l2.y = __float2bfloat16(y - __bfloat162float(h2.y));
    hi = *(uint32_t*)&h2; lo = *(uint32_t*)&l2;
}
__device__ __forceinline__ void hfsplit2(float x, float y, uint32_t& hi, uint32_t& lo) {
    __half2 h2, l2;
    h2.x = __float2half(x); h2.y = __float2half(y);
    l2.x = __float2half(x - __half2float(h2.x));
    l2.y = __float2half(y - __half2float(h2.y));
    hi = *(uint32_t*)&h2; lo = *(uint32_t*)&l2;
}

// ================= scratch =================
__device__ __half g_xh[BB*TE*DIMM];
__device__ __half g_xl[BB*TE*DIMM];
__device__ __half g_wqkvh[DIMM*DIMM];
__device__ __half g_wsh[NSSM*DD*DIMM];
__device__ __half g_wph[DIMM*DIMM];
__device__ __half g_cath[BB*TT*DIMM];
__device__ __half g_catl[BB*TT*DIMM];
__device__ __nv_bfloat16 g_qh[BB*NATTN*TE*DD];
__device__ __nv_bfloat16 g_ql[BB*NATTN*TE*DD];
__device__ __nv_bfloat16 g_kh[BB*NKV*TE*DD];
__device__ __nv_bfloat16 g_kl[BB*NKV*TE*DD];
__device__ __nv_bfloat16 g_vh[BB*NKV*TE*DD];
__device__ __nv_bfloat16 g_vl[BB*NKV*TE*DD];
__device__ float  g_qkv [BB*TE*DIMM];
__device__ float  g_ssmx[BB*TT*NSSM*DD];
__device__ float2 g_au  [BB*NSSM*TT*SS];
__device__ float  g_cc  [BB*NSSM*TT*SS];
__device__ float  g_hbuf[BB*NSSM*TT*SS];
__device__ float  g_pp  [BB*NSSM*TT*SS];
__device__ float2 g_carry[BB*NSSM*SS*SC_C];
__device__ float  g_hin [BB*NSSM*SS*SC_C];
__device__ float  g_pO [BB*NATTN*NQT*5*64*64];
__device__ float2 g_pml[BB*NATTN*NQT*5*64];

__device__ __forceinline__ void chunk_map(int c, int& qt, int& ci) {
    if (c < 8)       { qt = c;                ci = 0; }
    else if (c < 24) { qt = 8 + ((c-8) >> 1); ci = (c-8) & 1; }
    else if (c < 48) { qt = 16 + (c-24)/3;    ci = (c-24) % 3; }
    else if (c < 80) { qt = 24 + ((c-48)>>2); ci = (c-48) & 3; }
    else             { qt = 32;               ci = c - 80; }
}

// ================= fused conversion: x -> fp16 hi/lo; weights -> fp16 hi =================
#define CV_XN (BB*TE*DIMM)
#define CV_W1 (DIMM*DIMM)
#define CV_W2 (NSSM*DD*DIMM)
#define CV_W3 (DIMM*DIMM)
__global__ void conv_all_kernel(const float* __restrict__ x, const float* __restrict__ meta,
                                const float* __restrict__ qw, const float* __restrict__ kw,
                                const float* __restrict__ vw, const float* __restrict__ sw,
                                const float* __restrict__ pw)
{
    int idx = blockIdx.x*256 + threadIdx.x;
    if (idx < CV_XN) {
        int c = idx & 1023, row = idx >> 10;
        int b = row / TE, t = row % TE;
        float v = (t < NMETA) ? meta[t*DIMM + c] : x[((size_t)(b*TT) + (t-NMETA))*DIMM + c];
        __half h = __float2half(v);
        g_xh[idx] = h;
        g_xl[idx] = __float2half(v - __half2float(h));
    } else if (idx < CV_XN + CV_W1) {
        int j = idx - CV_XN; int r = j >> 10, c = j & 1023;
        float v;
        if (r < 512)      v = qw[r*DIMM + c];
        else if (r < 768) v = kw[(r-512)*DIMM + c];
        else              v = vw[(r-768)*DIMM + c];
        g_wqkvh[j] = __float2half(v);
    } else if (idx < CV_XN + CV_W1 + CV_W2) {
        int j = idx - CV_XN - CV_W1;
        g_wsh[j] = __float2half(sw[j]);
    } else if (idx < CV_XN + CV_W1 + CV_W2 + CV_W3) {
        int j = idx - CV_XN - CV_W1 - CV_W2;
        g_wph[j] = __float2half(pw[j]);
    }
}

// ================= HMMA GEMM: C = A @ B^T, 2-pass fp16 (Ah.Bh + Al.Bh) =================
// K-chunk 64 (128B fp16 rows). Stage: Ah 16K | Al 16K | Bh 16K = 48KB. 2 stages = 96KB.
__global__ void __launch_bounds__(256, 2) gemm_mma_kernel(
    const __half* __restrict__ Ah, const __half* __restrict__ Al,
    const __half* __restrict__ Bh,
    float* __restrict__ C, int M, int N, int remap)
{
    extern __shared__ char smc[];
    const uint32_t smb = smem_u32(smc);
    const int tid = threadIdx.x, l = tid & 31, w = tid >> 5;
    const int wm = w & 3, wn = w >> 2;
    const int m0 = blockIdx.y << 7, n0 = blockIdx.x << 7;

    float acc[2][8][4];
#pragma unroll
    for (int mi = 0; mi < 2; mi++)
#pragma unroll
        for (int nf = 0; nf < 8; nf++)
#pragma unroll
            for (int q = 0; q < 4; q++) acc[mi][nf][q] = 0.f;

    // fill stage st with chunk c (64 k-elems): 3 tiles x 1024 x 16B
    auto fill = [&](int st, int c) {
        for (int i = tid; i < 3072; i += 256) {
            int tile = i >> 10, idx = i & 1023, row = idx >> 3, seg = idx & 7;
            uint32_t dst = smb + st*49152 + tile*16384 + row*128 + ((seg*16) ^ ((row & 7) << 4));
            const __half* base;
            int grow, ok = 1;
            if (tile < 2) {
                grow = m0 + row;
                ok = grow < M;
                if (!ok) grow = 0;
                else if (remap) grow += 4*((grow >> 11) + 1);
                base = (tile == 0) ? Ah : Al;
            } else {
                grow = n0 + row;
                base = Bh;
            }
            const void* src = base + ((size_t)grow << 10) + c*64 + seg*8;
            cpasync16(dst, src, ok ? 16 : 0);
        }
        CP_COMMIT();
    };

    fill(0, 0);
    for (int c = 0; c < 16; c++) {
        const int st = c & 1;
        CP_WAIT0();
        __syncthreads();
        if (c + 1 < 16) fill(st ^ 1, c + 1);

        const uint32_t sA  = smb + st*49152;
        const uint32_t sAl = sA + 16384;
        const uint32_t sB  = sA + 32768;
#pragma unroll
        for (int kk = 0; kk < 4; kk++) {
            uint32_t aH[2][4], aL[2][4], b[8][2];
#pragma unroll
            for (int mi = 0; mi < 2; mi++) {
                int row = wm*32 + mi*16 + (l & 15);
                int kb = kk*32 + ((l >> 4) << 4);
                uint32_t sw = (uint32_t)((row & 7) << 4);
                ldsm4(aH[mi], sA  + row*128 + (kb ^ sw));
                ldsm4(aL[mi], sAl + row*128 + (kb ^ sw));
            }
#pragma unroll
            for (int nj = 0; nj < 4; nj++) {
                int row = wn*64 + nj*16 + (l & 7) + ((l >> 4) << 3);
                int kb = kk*32 + (((l >> 3) & 1) << 4);
                uint32_t t[4];
                ldsm4(t, sB + row*128 + (kb ^ ((row & 7) << 4)));
                b[nj*2][0]=t[0]; b[nj*2][1]=t[1]; b[nj*2+1][0]=t[2]; b[nj*2+1][1]=t[3];
            }
#pragma unroll
            for (int mi = 0; mi < 2; mi++)
#pragma unroll
                for (int nf = 0; nf < 8; nf++) {
                    mma16816h(acc[mi][nf], aH[mi], b[nf]);
                    mma16816h(acc[mi][nf], aL[mi], b[nf]);
                }
        }
        __syncthreads();
    }

#pragma unroll
    for (int mi = 0; mi < 2; mi++) {
        int m = m0 + wm*32 + mi*16 + (l >> 2);
#pragma unroll
        for (int nf = 0; nf < 8; nf++) {
            int n = n0 + wn*64 + nf*8 + ((l & 3) << 1);
            if (m < M)
                *(float2*)&C[(size_t)m*N + n] = make_float2(acc[mi][nf][0], acc[mi][nf][1]);
            if (m + 8 < M)
                *(float2*)&C[(size_t)(m+8)*N + n] = make_float2(acc[mi][nf][2], acc[mi][nf][3]);
        }
    }
}

// ================= RMSNorm + RoPE (+q_gain) -> bf16 hi/lo; V convert =================
__global__ void normrot_kernel(const float* __restrict__ qgain)
{
    const int QROWS = BB*NATTN*TE;
    const int KROWS = BB*NKV*TE;
    const int VROWS = BB*NKV*TE;
    int gw = (blockIdx.x*blockDim.x + threadIdx.x) >> 5;
    int lane = threadIdx.x & 31;
    if (gw >= QROWS + KROWS + VROWS) return;

    if (gw < QROWS + KROWS) {
        const float* src; __nv_bfloat16 *dh, *dl; size_t doff; float gain; int t;
        if (gw < QROWS) {
            int b = gw / (NATTN*TE); int r = gw % (NATTN*TE); int h = r / TE; t = r % TE;
            src = &g_qkv[((size_t)(b*TE)+t)*DIMM + h*DD];
            doff = (((size_t)(b*NATTN+h))*TE + t)*DD;
            dh = g_qh; dl = g_ql;
            gain = qgain[h];
        } else {
            int w2 = gw - QROWS;
            int b = w2 / (NKV*TE); int r = w2 % (NKV*TE); int h = r / TE; t = r % TE;
            src = &g_qkv[((size_t)(b*TE)+t)*DIMM + 512 + h*DD];
            doff = (((size_t)(b*NKV+h))*TE + t)*DD;
            dh = g_kh; dl = g_kl;
            gain = 1.0f;
        }
        float x1 = src[lane], x2 = src[lane+32];
        float ss = x1*x1 + x2*x2;
#pragma unroll
        for (int o = 16; o > 0; o >>= 1) ss += __shfl_xor_sync(0xffffffffu, ss, o);
        float rinv = rsqrtf(ss*(1.0f/64.0f) + 1e-6f);
        x1 *= rinv; x2 *= rinv;
        float inv = expf(-(float)lane * 0.28782313662425575f);
        float f = (float)t * inv;
        float sn, cs; sincosf(f, &sn, &cs);
        float y1 = (x1*cs - x2*sn) * gain;
        float y2 = (x1*sn + x2*cs) * gain;
        __nv_bfloat16 h1 = __float2bfloat16(y1), h2 = __float2bfloat16(y2);
        dh[doff + lane]      = h1;
        dh[doff + lane + 32] = h2;
        dl[doff + lane]      = __float2bfloat16(y1 - __bfloat162float(h1));
        dl[doff + lane + 32] = __float2bfloat16(y2 - __bfloat162float(h2));
    } else {
        int w2 = gw - QROWS - KROWS;
        int b = w2 / (NKV*TE); int r = w2 % (NKV*TE); int h = r / TE; int t = r % TE;
        const float* src = &g_qkv[((size_t)(b*TE)+t)*DIMM + 768 + h*DD];
        size_t doff = (((size_t)(b*NKV+h))*TE + t)*DD;
        float v1 = src[lane], v2 = src[lane+32];
        __nv_bfloat16 h1 = __float2bfloat16(v1), h2 = __float2bfloat16(v2);
        g_vh[doff + lane]      = h1;
        g_vh[doff + lane + 32] = h2;
        g_vl[doff + lane]      = __float2bfloat16(v1 - __bfloat162float(h1));
        g_vl[doff + lane + 32] = __float2bfloat16(v2 - __bfloat162float(h2));
    }
}

// ================= HMMA flash attention, split-KV chunks =================
__global__ void __launch_bounds__(128) attn_mma_kernel(const float* __restrict__ attn_scale)
{
    extern __shared__ char smc[];
    const uint32_t smb = smem_u32(smc);
    const int b = blockIdx.z, h = blockIdx.y;
    int qt, ci;
    chunk_map(ACH_PER_BH - 1 - (int)blockIdx.x, qt, ci);
    const int nch = (qt >> 3) + 1;
    const int q0 = qt << 6;
    const int kt_begin = ci << 3;
    const int kt_end = min(kt_begin + 8, qt + 1);
    const int hkv = h >> 1;
    const int tid = threadIdx.x, l = tid & 31, w = tid >> 5;

    const size_t qbase = ((size_t)(b*NATTN+h))*TE;
    const size_t kvbase = ((size_t)(b*NKV+hkv))*TE;

    auto loadK = [&](int k0) {
        for (int i = tid; i < 1024; i += 128) {
            int tile = i >> 9, idx = i & 511, row = idx >> 3, seg = idx & 7;
            uint32_t dst = smb + 16384 + tile*8192 + row*128 + ((seg*16) ^ ((row & 7) << 4));
            int krow = k0 + row;
            int ok = krow < TE;
            const __nv_bfloat16* base = tile ? g_kl : g_kh;
            cpasync16(dst, base + (kvbase + (ok ? krow : 0))*DD + seg*8, ok ? 16 : 0);
        }
        CP_COMMIT();
    };
    auto loadV = [&](int k0) {
        for (int i = tid; i < 1024; i += 128) {
            int tile = i >> 9, idx = i & 511, row = idx >> 3, seg = idx & 7;
            uint32_t dst = smb + 32768 + tile*8192 + row*128 + ((seg*16) ^ ((row & 7) << 4));
            int krow = k0 + row;
            int ok = krow < TE;
            const __nv_bfloat16* base = tile ? g_vl : g_vh;
            cpasync16(dst, base + (kvbase + (ok ? krow : 0))*DD + seg*8, ok ? 16 : 0);
        }
        CP_COMMIT();
    };

    {
        for (int i = tid; i < 1024; i += 128) {
            int tile = i >> 9, idx = i & 511, row = idx >> 3, seg = idx & 7;
            uint32_t dst = smb + tile*8192 + row*128 + ((seg*16) ^ ((row & 7) << 4));
            int qrow = q0 + row;
            int ok = qrow < TE;
            const __nv_bfloat16* base = tile ? g_ql : g_qh;
            cpasync16(dst, base + (qbase + (ok ? qrow : 0))*DD + seg*8, ok ? 16 : 0);
        }
        for (int i = tid; i < 1024; i += 128) {
            int tile = i >> 9, idx = i & 511, row = idx >> 3, seg = idx & 7;
            uint32_t dst = smb + 16384 + tile*8192 + row*128 + ((seg*16) ^ ((row & 7) << 4));
            int krow = (kt_begin << 6) + row;
            int ok = krow < TE;
            const __nv_bfloat16* base = tile ? g_kl : g_kh;
            cpasync16(dst, base + (kvbase + (ok ? krow : 0))*DD + seg*8, ok ? 16 : 0);
        }
        CP_COMMIT();
        loadV(kt_begin << 6);
    }

    float sO[8][4];
#pragma unroll
    for (int nf = 0; nf < 8; nf++)
#pragma unroll
        for (int q = 0; q < 4; q++) sO[nf][q] = 0.f;
    float m0r = -1e30f, m1r = -1e30f, l0r = 0.f, l1r = 0.f;

    const int grow0 = q0 + w*16 + (l >> 2);
    const int grow1 = grow0 + 8;

    for (int kt = kt_begin; kt < kt_end; kt++) {
        const int k0 = kt << 6;
        CP_WAIT1();
        __syncthreads();

        float s[8][4];
#pragma unroll
        for (int nf = 0; nf < 8; nf++)
#pragma unroll
            for (int q = 0; q < 4; q++) s[nf][q] = 0.f;

#pragma unroll
        for (int kc = 0; kc < 4; kc++) {
            uint32_t aH[4], aL[4], bk[8][2];
            {
                int row = w*16 + (l & 15);
                int kb = kc*32 + ((l >> 4) << 4);
                uint32_t ad = smb + row*128 + (kb ^ ((row & 7) << 4));
                ldsm4(aH, ad);
                ldsm4(aL, ad + 8192);
            }
#pragma unroll
            for (int nj = 0; nj < 4; nj++) {
                int row = nj*16 + (l & 7) + ((l >> 4) << 3);
                int kb = kc*32 + (((l >> 3) & 1) << 4);
                uint32_t bd = smb + 16384 + row*128 + (kb ^ ((row & 7) << 4));
                uint32_t t[4];
                ldsm4(t, bd);
                bk[nj*2][0]=t[0]; bk[nj*2][1]=t[1]; bk[nj*2+1][0]=t[2]; bk[nj*2+1][1]=t[3];
            }
#pragma unroll
            for (int nf = 0; nf < 8; nf++) {
                mma16816(s[nf], aH, bk[nf]);
                mma16816(s[nf], aL, bk[nf]);
            }
#pragma unroll
            for (int nj = 0; nj < 4; nj++) {
                int row = nj*16 + (l & 7) + ((l >> 4) << 3);
                int kb = kc*32 + (((l >> 3) & 1) << 4);
                uint32_t bd = smb + 24576 + row*128 + (kb ^ ((row & 7) << 4));
                uint32_t t[4];
                ldsm4(t, bd);
                bk[nj*2][0]=t[0]; bk[nj*2][1]=t[1]; bk[nj*2+1][0]=t[2]; bk[nj*2+1][1]=t[3];
            }
#pragma unroll
            for (int nf = 0; nf < 8; nf++)
                mma16816(s[nf], aH, bk[nf]);
        }
        __syncthreads();
        if (kt + 1 < kt_end) loadK((kt + 1) << 6);

        const bool diag = (kt == qt);
#pragma unroll
        for (int nf = 0; nf < 8; nf++) {
            int c0 = k0 + nf*8 + ((l & 3) << 1);
            s[nf][0] *= 0.125f; s[nf][1] *= 0.125f;
            s[nf][2] *= 0.125f; s[nf][3] *= 0.125f;
            if (diag) {
                if (c0     > grow0) s[nf][0] = -1e30f;
                if (c0 + 1 > grow0) s[nf][1] = -1e30f;
                if (c0     > grow1) s[nf][2] = -1e30f;
                if (c0 + 1 > grow1) s[nf][3] = -1e30f;
            }
        }

        float mx0 = -1e30f, mx1 = -1e30f;
#pragma unroll
        for (int nf = 0; nf < 8; nf++) {
            mx0 = fmaxf(mx0, fmaxf(s[nf][0], s[nf][1]));
            mx1 = fmaxf(mx1, fmaxf(s[nf][2], s[nf][3]));
        }
        mx0 = fmaxf(mx0, __shfl_xor_sync(0xffffffffu, mx0, 1));
        mx0 = fmaxf(mx0, __shfl_xor_sync(0xffffffffu, mx0, 2));
        mx1 = fmaxf(mx1, __shfl_xor_sync(0xffffffffu, mx1, 1));
        mx1 = fmaxf(mx1, __shfl_xor_sync(0xffffffffu, mx1, 2));
        float mn0 = fmaxf(m0r, mx0), mn1 = fmaxf(m1r, mx1);
        float al0 = __expf(m0r - mn0), al1 = __expf(m1r - mn1);
        m0r = mn0; m1r = mn1;

        float rs0 = 0.f, rs1 = 0.f;
#pragma unroll
        for (int nf = 0; nf < 8; nf++) {
            float p0 = __expf(s[nf][0] - mn0), p1 = __expf(s[nf][1] - mn0);
            float p2 = __expf(s[nf][2] - mn1), p3 = __expf(s[nf][3] - mn1);
            rs0 += p0 + p1; rs1 += p2 + p3;
            s[nf][0] = p0; s[nf][1] = p1; s[nf][2] = p2; s[nf][3] = p3;
        }
        rs0 += __shfl_xor_sync(0xffffffffu, rs0, 1);
        rs0 += __shfl_xor_sync(0xffffffffu, rs0, 2);
        rs1 += __shfl_xor_sync(0xffffffffu, rs1, 1);
        rs1 += __shfl_xor_sync(0xffffffffu, rs1, 2);
        l0r = l0r*al0 + rs0;
        l1r = l1r*al1 + rs1;

#pragma unroll
        for (int nf = 0; nf < 8; nf++) {
            sO[nf][0] *= al0; sO[nf][1] *= al0;
            sO[nf][2] *= al1; sO[nf][3] *= al1;
        }

        if (kt + 1 < kt_end) { CP_WAIT1(); } else { CP_WAIT0(); }
        __syncthreads();

#pragma unroll
        for (int kc = 0; kc < 4; kc++) {
            uint32_t pH[4], pL[4], bv[8][2];
            bfsplit2(s[2*kc][0],   s[2*kc][1],   pH[0], pL[0]);
            bfsplit2(s[2*kc][2],   s[2*kc][3],   pH[1], pL[1]);
            bfsplit2(s[2*kc+1][0], s[2*kc+1][1], pH[2], pL[2]);
            bfsplit2(s[2*kc+1][2], s[2*kc+1][3], pH[3], pL[3]);
#pragma unroll
            for (int i2 = 0; i2 < 4; i2++) {
                int row = kc*16 + (l & 7) + (((l >> 3) & 1) << 3);
                int cb = i2*32 + (((l >> 4) & 1) << 4);
                uint32_t vd = smb + 32768 + row*128 + (cb ^ ((row & 7) << 4));
                uint32_t t[4];
                ldsm4t(t, vd);
                bv[2*i2][0]=t[0]; bv[2*i2][1]=t[1]; bv[2*i2+1][0]=t[2]; bv[2*i2+1][1]=t[3];
            }
#pragma unroll
            for (int nf = 0; nf < 8; nf++) {
                mma16816(sO[nf], pH, bv[nf]);
                mma16816(sO[nf], pL, bv[nf]);
            }
#pragma unroll
            for (int i2 = 0; i2 < 4; i2++) {
                int row = kc*16 + (l & 7) + (((l >> 3) & 1) << 3);
                int cb = i2*32 + (((l >> 4) & 1) << 4);
                uint32_t vd = smb + 40960 + row*128 + (cb ^ ((row & 7) << 4));
                uint32_t t[4];
                ldsm4t(t, vd);
                bv[2*i2][0]=t[0]; bv[2*i2][1]=t[1]; bv[2*i2+1][0]=t[2]; bv[2*i2+1][1]=t[3];
            }
#pragma unroll
            for (int nf = 0; nf < 8; nf++)
                mma16816(sO[nf], pH, bv[nf]);
        }
        __syncthreads();
        if (kt + 1 < kt_end) loadV((kt + 1) << 6);
    }

    if (nch == 1) {
        float ascale = attn_scale[0];
        float inv0 = ascale / l0r, inv1 = ascale / l1r;
#pragma unroll
        for (int nf = 0; nf < 8; nf++) {
            int oc = h*DD + nf*8 + ((l & 3) << 1);
            if (grow0 >= NMETA && grow0 < TE) {
                uint32_t hi, lo; hfsplit2(sO[nf][0]*inv0, sO[nf][1]*inv0, hi, lo);
                size_t base = ((size_t)(b*TT) + (grow0 - NMETA))*DIMM + oc;
                *(uint32_t*)&g_cath[base] = hi;
                *(uint32_t*)&g_catl[base] = lo;
            }
            if (grow1 >= NMETA && grow1 < TE) {
                uint32_t hi, lo; hfsplit2(sO[nf][2]*inv1, sO[nf][3]*inv1, hi, lo);
                size_t base = ((size_t)(b*TT) + (grow1 - NMETA))*DIMM + oc;
                *(uint32_t*)&g_cath[base] = hi;
                *(uint32_t*)&g_catl[base] = lo;
            }
        }
    } else {
        const int slot = (((b*NATTN+h)*NQT) + qt)*5 + ci;
        float* po = g_pO + (size_t)slot*4096;
        const int r0 = w*16 + (l >> 2), r1 = r0 + 8;
#pragma unroll
        for (int nf = 0; nf < 8; nf++) {
            int ccol = nf*8 + ((l & 3) << 1);
            *(float2*)&po[r0*64 + ccol] = make_float2(sO[nf][0], sO[nf][1]);
            *(float2*)&po[r1*64 + ccol] = make_float2(sO[nf][2], sO[nf][3]);
        }
        if ((l & 3) == 0) {
            g_pml[(size_t)slot*64 + r0] = make_float2(m0r, l0r);
            g_pml[(size_t)slot*64 + r1] = make_float2(m1r, l1r);
        }
    }
}

// ================= attention merge (qt >= 8) =================
__global__ void __launch_bounds__(256) attn_merge_kernel(const float* __restrict__ attn_scale)
{
    const int b = blockIdx.z, h = blockIdx.y;
    const int qt = 8 + (int)blockIdx.x;
    const int nch = (qt >> 3) + 1;
    const int tid = threadIdx.x;
    const int r = tid >> 2, cg = (tid & 3) << 4;
    const int slot0 = (((b*NATTN+h)*NQT) + qt)*5;

    float mi[5], li[5];
    float mstar = -1e30f;
    for (int ci = 0; ci < nch; ci++) {
        float2 ml = g_pml[(size_t)(slot0+ci)*64 + r];
        mi[ci] = ml.x; li[ci] = ml.y;
        mstar = fmaxf(mstar, ml.x);
    }
    float L = 0.f;
    float wf[5];
    for (int ci = 0; ci < nch; ci++) {
        wf[ci] = __expf(mi[ci] - mstar);
        L += wf[ci]*li[ci];
    }
    float acc[16];
#pragma unroll
    for (int j = 0; j < 16; j++) acc[j] = 0.f;
    for (int ci = 0; ci < nch; ci++) {
        const float* po = g_pO + (size_t)(slot0+ci)*4096 + r*64 + cg;
        float wfc = wf[ci];
#pragma unroll
        for (int j = 0; j < 16; j += 4) {
            float4 v = *(const float4*)&po[j];
            acc[j]   += wfc*v.x; acc[j+1] += wfc*v.y;
            acc[j+2] += wfc*v.z; acc[j+3] += wfc*v.w;
        }
    }
    int q = (qt << 6) + r;
    if (q >= NMETA && q < TE) {
        float sc = attn_scale[0] / L;
        size_t base = ((size_t)(b*TT) + (q - NMETA))*DIMM + h*DD + cg;
#pragma unroll
        for (int j = 0; j < 16; j += 2) {
            uint32_t hi, lo;
            hfsplit2(acc[j]*sc, acc[j+1]*sc, hi, lo);
            *(uint32_t*)&g_cath[base + j] = hi;
            *(uint32_t*)&g_catl[base + j] = lo;
        }
    }
}

// ================= SSM: dt / a / Bx / Cc =================
__global__ void dtbc_kernel(const float* __restrict__ dtw, const float* __restrict__ dtb,
                            const float* __restrict__ Bw,  const float* __restrict__ Cw,
                            const float* __restrict__ logA)
{
    __shared__ float xs[64][65];
    __shared__ float ws[48][65];
    __shared__ float dts[64][16];
    const int b = blockIdx.z, h = blockIdx.y, t0 = blockIdx.x*64;
    const int tid = threadIdx.x;

    for (int idx = tid; idx < 48*64; idx += 256) {
        int o = idx >> 6, k = idx & 63;
        float v;
        if (o < 16)      v = dtw[(h*16+o)*64 + k];
        else if (o < 32) v = Bw[(h*16+(o-16))*64 + k];
        else             v = Cw[(h*16+(o-32))*64 + k];
        ws[o][k] = v;
    }
    for (int idx = tid; idx < 64*64; idx += 256) {
        int r = idx >> 6, k = idx & 63;
        xs[r][k] = g_ssmx[((size_t)(b*TT)+t0+r)*(NSSM*DD) + h*DD + k];
    }
    __syncthreads();

    const int r = tid >> 2;
    const size_t obase = (((size_t)(b*NSSM+h))*TT + t0 + r)*SS;

    {
        int so = (tid & 3) << 2;
#pragma unroll
        for (int q = 0; q < 4; q++) {
            int o = so + q;
            float d = 0.f;
#pragma unroll
            for (int k = 0; k < 64; k++) d += xs[r][k]*ws[o][k];
            d += dtb[h*16 + o];
            float sp = (d > 20.f) ? d : log1pf(expf(d));
            float dt = fminf(sp, 1.0f);
            dts[r][o] = dt;
            float A  = fminf(-expf(logA[h*16 + o]), 10.0f);
            float la = fminf(fmaxf(dt*A, -0.5f), 0.0f);
            g_au[obase + o].x = expf(la);
        }
    }
    __syncthreads();
    {
        int jo = (tid & 3) << 3;
#pragma unroll
        for (int q = 0; q < 8; q++) {
            int o2 = jo + q;
            float d = 0.f;
#pragma unroll
            for (int k = 0; k < 64; k++) d += xs[r][k]*ws[16+o2][k];
            if (o2 < 16) g_au[obase + o2].y     = d * dts[r][o2];
            else         g_cc[obase + (o2-16)]  = d;
        }
    }
}

// ================= scan phase 1 =================
__global__ void scan1_kernel()
{
    const int bh = blockIdx.x >> 2, cg = blockIdx.x & 3;
    const int s = threadIdx.x & 15, ckl = threadIdx.x >> 4;
    const int chunk = cg*16 + ckl;
    const int t0 = chunk*SC_L;
    const size_t base = (size_t)bh*TT*SS + s;

    float hv = 0.f, p = 1.f;
#pragma unroll 4
    for (int t = 0; t < SC_L; t++) {
        size_t o = base + (size_t)(t0 + t)*SS;
        float2 au = g_au[o];
        p *= au.x;
        hv = fmaf(au.x, hv, au.y);
        g_hbuf[o] = hv;
        g_pp[o] = p;
    }
    g_carry[(bh*SS + s)*SC_C + chunk] = make_float2(hv, p);
}

// ================= scan phase 2 =================
__global__ void scan2_kernel()
{
    int lane = blockIdx.x*64 + threadIdx.x;
    if (lane >= BB*NSSM*SS) return;
    float hin = 0.f;
    const int cb = lane*SC_C;
#pragma unroll 4
    for (int c = 0; c < SC_C; c++) {
        g_hin[cb + c] = hin;
        float2 cr = g_carry[cb + c];
        hin = fmaf(cr.y, hin, cr.x);
    }
}

// ================= SSM epilogue =================
__global__ void ssmout_kernel(const float* __restrict__ Ow, const float* __restrict__ ssm_scale)
{
    __shared__ float hs[64][17];
    __shared__ float cs[64][17];
    __shared__ float ows[64][17];
    const int b = blockIdx.z, h = blockIdx.y, t0 = blockIdx.x*64;
    const int tid = threadIdx.x;
    const int bh = b*NSSM + h;

    for (int idx = tid; idx < 64*16; idx += 256) {
        int r = idx >> 4, s = idx & 15;
        int t = t0 + r;
        size_t src = ((size_t)bh*TT + t)*SS + s;
        float hin = g_hin[(bh*SS + s)*SC_C + (t >> 5)];
        hs[r][s] = fmaf(g_pp[src], hin, g_hbuf[src]);
        cs[r][s] = g_cc[src];
        ows[r][s] = Ow[(h*64 + r)*16 + s];
    }
    __syncthreads();

    const int r = tid >> 2, dp = tid & 3;
    float y = 0.f;
#pragma unroll
    for (int s = 0; s < 16; s++) y += cs[r][s]*hs[r][s];
    float x0 = g_ssmx[((size_t)(b*TT)+t0+r)*(NSSM*DD) + h*DD];
    float sc = ssm_scale[0];
    float yx = y * x0;
    size_t ob = ((size_t)(b*TT)+t0+r)*DIMM + 512 + h*DD + dp*16;
#pragma unroll
    for (int q = 0; q < 16; q += 2) {
        int d = dp*16 + q;
        float v0 = yx, v1 = yx;
#pragma unroll
        for (int s = 0; s < 16; s++) {
            v0 += hs[r][s]*ows[d][s];
            v1 += hs[r][s]*ows[d+1][s];
        }
        v0 *= sc; v1 *= sc;
        uint32_t hi, lo;
        hfsplit2(v0, v1, hi, lo);
        *(uint32_t*)&g_cath[ob + q] = hi;
        *(uint32_t*)&g_catl[ob + q] = lo;
    }
}

// ================= launch =================
extern "C" void kernel_launch(void* const* d_in, const int* in_sizes, int n_in,
                              void* d_out, int out_size)
{
    const float* x         = (const float*)d_in[0];
    const float* meta      = (const float*)d_in[1];
    const float* qw        = (const float*)d_in[2];
    const float* kw        = (const float*)d_in[3];
    const float* vw        = (const float*)d_in[4];
    const float* qgain     = (const float*)d_in[5];
    const float* ssm_in_w  = (const float*)d_in[6];
    const float* projw     = (const float*)d_in[7];
    const float* attn_sc   = (const float*)d_in[8];
    const float* ssm_sc    = (const float*)d_in[9];
    const float* logA      = (const float*)d_in[10];
    const float* Bw        = (const float*)d_in[11];
    const float* Cw        = (const float*)d_in[12];
    const float* dtw       = (const float*)d_in[13];
    const float* dtb       = (const float*)d_in[14];
    const float* Ow        = (const float*)d_in[15];
    float* out = (float*)d_out;

    __half *p_xh, *p_xl, *p_wqh, *p_wsh, *p_wph, *p_cth, *p_ctl;
    float *p_qkv, *p_ssmx;
    cudaGetSymbolAddress((void**)&p_xh,  g_xh);
    cudaGetSymbolAddress((void**)&p_xl,  g_xl);
    cudaGetSymbolAddress((void**)&p_wqh, g_wqkvh);
    cudaGetSymbolAddress((void**)&p_wsh, g_wsh);
    cudaGetSymbolAddress((void**)&p_wph, g_wph);
    cudaGetSymbolAddress((void**)&p_cth, g_cath);
    cudaGetSymbolAddress((void**)&p_ctl, g_catl);
    cudaGetSymbolAddress((void**)&p_qkv,  g_qkv);
    cudaGetSymbolAddress((void**)&p_ssmx, g_ssmx);

    const int GEMM_SMEM = 2*49152;                                // 98304
    cudaFuncSetAttribute(gemm_mma_kernel, cudaFuncAttributeMaxDynamicSharedMemorySize, GEMM_SMEM);
    const int ATTN_SMEM = 6*8192;
    cudaFuncSetAttribute(attn_mma_kernel, cudaFuncAttributeMaxDynamicSharedMemorySize, ATTN_SMEM);

    const int CV_TOTAL = CV_XN + CV_W1 + CV_W2 + CV_W3;

    conv_all_kernel<<<(CV_TOTAL + 255)/256, 256>>>(x, meta, qw, kw, vw, ssm_in_w, projw);
    gemm_mma_kernel<<<dim3(DIMM/128, (BB*TE + 127)/128), 256, GEMM_SMEM>>>(
        p_xh, p_xl, p_wqh, p_qkv, BB*TE, DIMM, 0);
    {
        int warps = BB*(NATTN + NKV + NKV)*TE;
        normrot_kernel<<<(warps*32 + 255)/256, 256>>>(qgain);
    }
    attn_mma_kernel<<<dim3(ACH_PER_BH, NATTN, BB), 128, ATTN_SMEM>>>(attn_sc);
    attn_merge_kernel<<<dim3(NQT - 8, NATTN, BB), 256>>>(attn_sc);
    gemm_mma_kernel<<<dim3((NSSM*DD)/128, (BB*TT)/128), 256, GEMM_SMEM>>>(
        p_xh, p_xl, p_wsh, p_ssmx, BB*TT, NSSM*DD, 1);
    dtbc_kernel<<<dim3(TT/64, NSSM, BB), 256>>>(dtw, dtb, Bw, Cw, logA);
    scan1_kernel<<<64, 256>>>();
    scan2_kernel<<<4, 64>>>();
    ssmout_kernel<<<dim3(TT/64, NSSM, BB), 256>>>(Ow, ssm_sc);
    gemm_mma_kernel<<<dim3(DIMM/128, (BB*TT)/128), 256, GEMM_SMEM>>>(
        p_cth, p_ctl, p_wph, out, BB*TT, DIMM, 0);
}

// round 15
// speedup vs baseline: 1.7897x; 1.0678x over previous
#include <cuda_runtime.h>
#include <cuda_bf16.h>
#include <cuda_fp16.h>
#include <math.h>
#include <stdint.h>

#define BB     2
#define TT     2048
#define TE     2052
#define DIMM   1024
#define DD     64
#define NATTN  8
#define NKV    4
#define NSSM   8
#define SS     16
#define NMETA  4

#define SC_C   64
#define SC_L   32
#define ACH_PER_BH 85
#define NQT 33

// ================= helpers =================
__device__ __forceinline__ uint32_t smem_u32(const void* p) {
    uint32_t a;
    asm("{ .reg .u64 t; cvta.to.shared.u64 t, %1; cvt.u32.u64 %0, t; }" : "=r"(a) : "l"(p));
    return a;
}
__device__ __forceinline__ void ldsm4(uint32_t* r, uint32_t addr) {
    asm volatile("ldmatrix.sync.aligned.m8n8.x4.shared.b16 {%0,%1,%2,%3}, [%4];"
        : "=r"(r[0]), "=r"(r[1]), "=r"(r[2]), "=r"(r[3]) : "r"(addr));
}
__device__ __forceinline__ void ldsm4t(uint32_t* r, uint32_t addr) {
    asm volatile("ldmatrix.sync.aligned.m8n8.x4.trans.shared.b16 {%0,%1,%2,%3}, [%4];"
        : "=r"(r[0]), "=r"(r[1]), "=r"(r[2]), "=r"(r[3]) : "r"(addr));
}
__device__ __forceinline__ void mma16816h(float* c, const uint32_t* a, const uint32_t* b) {
    asm volatile("mma.sync.aligned.m16n8k16.row.col.f32.f16.f16.f32 "
        "{%0,%1,%2,%3}, {%4,%5,%6,%7}, {%8,%9}, {%0,%1,%2,%3};"
        : "+f"(c[0]), "+f"(c[1]), "+f"(c[2]), "+f"(c[3])
        : "r"(a[0]), "r"(a[1]), "r"(a[2]), "r"(a[3]), "r"(b[0]), "r"(b[1]));
}
__device__ __forceinline__ void cpasync16(uint32_t dst, const void* src, int srcsize) {
    asm volatile("cp.async.cg.shared.global [%0], [%1], 16, %2;"
        :: "r"(dst), "l"(src), "r"(srcsize) : "memory");
}
#define CP_COMMIT() asm volatile("cp.async.commit_group;" ::: "memory")
#define CP_WAIT0()  asm volatile("cp.async.wait_group 0;" ::: "memory")
#define CP_WAIT1()  asm volatile("cp.async.wait_group 1;" ::: "memory")
__device__ __forceinline__ void hfsplit2(float x, float y, uint32_t& hi, uint32_t& lo) {
    __half2 h2, l2;
    h2.x = __float2half(x); h2.y = __float2half(y);
    l2.x = __float2half(x - __half2float(h2.x));
    l2.y = __float2half(y - __half2float(h2.y));
    hi = *(uint32_t*)&h2; lo = *(uint32_t*)&l2;
}

// ================= scratch =================
__device__ __half g_xh[BB*TE*DIMM];
__device__ __half g_xl[BB*TE*DIMM];
__device__ __half g_wqkvh[DIMM*DIMM];
__device__ __half g_wsh[NSSM*DD*DIMM];
__device__ __half g_wph[DIMM*DIMM];
__device__ __half g_cath[BB*TT*DIMM];
__device__ __half g_catl[BB*TT*DIMM];
__device__ __half g_qh[BB*NATTN*TE*DD];
__device__ __half g_ql[BB*NATTN*TE*DD];
__device__ __half g_kh[BB*NKV*TE*DD];
__device__ __half g_vh[BB*NKV*TE*DD];
__device__ float  g_qkv [BB*TE*DIMM];
__device__ float  g_ssmx[BB*TT*NSSM*DD];
__device__ float2 g_au  [BB*NSSM*TT*SS];
__device__ float  g_cc  [BB*NSSM*TT*SS];
__device__ float  g_hbuf[BB*NSSM*TT*SS];
__device__ float  g_pp  [BB*NSSM*TT*SS];
__device__ float2 g_carry[BB*NSSM*SS*SC_C];
__device__ float  g_hin [BB*NSSM*SS*SC_C];
__device__ float  g_pO [BB*NATTN*NQT*5*64*64];
__device__ float2 g_pml[BB*NATTN*NQT*5*64];

__device__ __forceinline__ void chunk_map(int c, int& qt, int& ci) {
    if (c < 8)       { qt = c;                ci = 0; }
    else if (c < 24) { qt = 8 + ((c-8) >> 1); ci = (c-8) & 1; }
    else if (c < 48) { qt = 16 + (c-24)/3;    ci = (c-24) % 3; }
    else if (c < 80) { qt = 24 + ((c-48)>>2); ci = (c-48) & 3; }
    else             { qt = 32;               ci = c - 80; }
}

// ================= fused conversion =================
#define CV_XN (BB*TE*DIMM)
#define CV_W1 (DIMM*DIMM)
#define CV_W2 (NSSM*DD*DIMM)
#define CV_W3 (DIMM*DIMM)
__global__ void conv_all_kernel(const float* __restrict__ x, const float* __restrict__ meta,
                                const float* __restrict__ qw, const float* __restrict__ kw,
                                const float* __restrict__ vw, const float* __restrict__ sw,
                                const float* __restrict__ pw)
{
    int idx = blockIdx.x*256 + threadIdx.x;
    if (idx < CV_XN) {
        int c = idx & 1023, row = idx >> 10;
        int b = row / TE, t = row % TE;
        float v = (t < NMETA) ? meta[t*DIMM + c] : x[((size_t)(b*TT) + (t-NMETA))*DIMM + c];
        __half h = __float2half(v);
        g_xh[idx] = h;
        g_xl[idx] = __float2half(v - __half2float(h));
    } else if (idx < CV_XN + CV_W1) {
        int j = idx - CV_XN; int r = j >> 10, c = j & 1023;
        float v;
        if (r < 512)      v = qw[r*DIMM + c];
        else if (r < 768) v = kw[(r-512)*DIMM + c];
        else              v = vw[(r-768)*DIMM + c];
        g_wqkvh[j] = __float2half(v);
    } else if (idx < CV_XN + CV_W1 + CV_W2) {
        int j = idx - CV_XN - CV_W1;
        g_wsh[j] = __float2half(sw[j]);
    } else if (idx < CV_XN + CV_W1 + CV_W2 + CV_W3) {
        int j = idx - CV_XN - CV_W1 - CV_W2;
        g_wph[j] = __float2half(pw[j]);
    }
}

// ================= HMMA GEMM: C = A @ B^T, 2-pass fp16 =================
__global__ void __launch_bounds__(256, 2) gemm_mma_kernel(
    const __half* __restrict__ Ah, const __half* __restrict__ Al,
    const __half* __restrict__ Bh,
    float* __restrict__ C, int M, int N, int remap)
{
    extern __shared__ char smc[];
    const uint32_t smb = smem_u32(smc);
    const int tid = threadIdx.x, l = tid & 31, w = tid >> 5;
    const int wm = w & 3, wn = w >> 2;
    const int m0 = blockIdx.y << 7, n0 = blockIdx.x << 7;

    float acc[2][8][4];
#pragma unroll
    for (int mi = 0; mi < 2; mi++)
#pragma unroll
        for (int nf = 0; nf < 8; nf++)
#pragma unroll
            for (int q = 0; q < 4; q++) acc[mi][nf][q] = 0.f;

    auto fill = [&](int st, int c) {
        for (int i = tid; i < 3072; i += 256) {
            int tile = i >> 10, idx = i & 1023, row = idx >> 3, seg = idx & 7;
            uint32_t dst = smb + st*49152 + tile*16384 + row*128 + ((seg*16) ^ ((row & 7) << 4));
            const __half* base;
            int grow, ok = 1;
            if (tile < 2) {
                grow = m0 + row;
                ok = grow < M;
                if (!ok) grow = 0;
                else if (remap) grow += 4*((grow >> 11) + 1);
                base = (tile == 0) ? Ah : Al;
            } else {
                grow = n0 + row;
                base = Bh;
            }
            const void* src = base + ((size_t)grow << 10) + c*64 + seg*8;
            cpasync16(dst, src, ok ? 16 : 0);
        }
        CP_COMMIT();
    };

    fill(0, 0);
    for (int c = 0; c < 16; c++) {
        const int st = c & 1;
        CP_WAIT0();
        __syncthreads();
        if (c + 1 < 16) fill(st ^ 1, c + 1);

        const uint32_t sA  = smb + st*49152;
        const uint32_t sAl = sA + 16384;
        const uint32_t sB  = sA + 32768;
#pragma unroll
        for (int kk = 0; kk < 4; kk++) {
            uint32_t aH[2][4], aL[2][4], b[8][2];
#pragma unroll
            for (int mi = 0; mi < 2; mi++) {
                int row = wm*32 + mi*16 + (l & 15);
                int kb = kk*32 + ((l >> 4) << 4);
                uint32_t sw = (uint32_t)((row & 7) << 4);
                ldsm4(aH[mi], sA  + row*128 + (kb ^ sw));
                ldsm4(aL[mi], sAl + row*128 + (kb ^ sw));
            }
#pragma unroll
            for (int nj = 0; nj < 4; nj++) {
                int row = wn*64 + nj*16 + (l & 7) + ((l >> 4) << 3);
                int kb = kk*32 + (((l >> 3) & 1) << 4);
                uint32_t t[4];
                ldsm4(t, sB + row*128 + (kb ^ ((row & 7) << 4)));
                b[nj*2][0]=t[0]; b[nj*2][1]=t[1]; b[nj*2+1][0]=t[2]; b[nj*2+1][1]=t[3];
            }
#pragma unroll
            for (int mi = 0; mi < 2; mi++)
#pragma unroll
                for (int nf = 0; nf < 8; nf++) {
                    mma16816h(acc[mi][nf], aH[mi], b[nf]);
                    mma16816h(acc[mi][nf], aL[mi], b[nf]);
                }
        }
        __syncthreads();
    }

#pragma unroll
    for (int mi = 0; mi < 2; mi++) {
        int m = m0 + wm*32 + mi*16 + (l >> 2);
#pragma unroll
        for (int nf = 0; nf < 8; nf++) {
            int n = n0 + wn*64 + nf*8 + ((l & 3) << 1);
            if (m < M)
                *(float2*)&C[(size_t)m*N + n] = make_float2(acc[mi][nf][0], acc[mi][nf][1]);
            if (m + 8 < M)
                *(float2*)&C[(size_t)(m+8)*N + n] = make_float2(acc[mi][nf][2], acc[mi][nf][3]);
        }
    }
}

// ================= RMSNorm + RoPE (+q_gain) -> fp16 (Q hi/lo, K hi, V hi) =================
__global__ void normrot_kernel(const float* __restrict__ qgain)
{
    const int QROWS = BB*NATTN*TE;
    const int KROWS = BB*NKV*TE;
    const int VROWS = BB*NKV*TE;
    int gw = (blockIdx.x*blockDim.x + threadIdx.x) >> 5;
    int lane = threadIdx.x & 31;
    if (gw >= QROWS + KROWS + VROWS) return;

    if (gw < QROWS + KROWS) {
        const float* src; size_t doff; float gain; int t; bool isQ;
        if (gw < QROWS) {
            int b = gw / (NATTN*TE); int r = gw % (NATTN*TE); int h = r / TE; t = r % TE;
            src = &g_qkv[((size_t)(b*TE)+t)*DIMM + h*DD];
            doff = (((size_t)(b*NATTN+h))*TE + t)*DD;
            gain = qgain[h]; isQ = true;
        } else {
            int w2 = gw - QROWS;
            int b = w2 / (NKV*TE); int r = w2 % (NKV*TE); int h = r / TE; t = r % TE;
            src = &g_qkv[((size_t)(b*TE)+t)*DIMM + 512 + h*DD];
            doff = (((size_t)(b*NKV+h))*TE + t)*DD;
            gain = 1.0f; isQ = false;
        }
        float x1 = src[lane], x2 = src[lane+32];
        float ss = x1*x1 + x2*x2;
#pragma unroll
        for (int o = 16; o > 0; o >>= 1) ss += __shfl_xor_sync(0xffffffffu, ss, o);
        float rinv = rsqrtf(ss*(1.0f/64.0f) + 1e-6f);
        x1 *= rinv; x2 *= rinv;
        float inv = expf(-(float)lane * 0.28782313662425575f);
        float f = (float)t * inv;
        float sn, cs; sincosf(f, &sn, &cs);
        float y1 = (x1*cs - x2*sn) * gain;
        float y2 = (x1*sn + x2*cs) * gain;
        __half h1 = __float2half(y1), h2 = __float2half(y2);
        if (isQ) {
            g_qh[doff + lane]      = h1;
            g_qh[doff + lane + 32] = h2;
            g_ql[doff + lane]      = __float2half(y1 - __half2float(h1));
            g_ql[doff + lane + 32] = __float2half(y2 - __half2float(h2));
        } else {
            g_kh[doff + lane]      = h1;
            g_kh[doff + lane + 32] = h2;
        }
    } else {
        int w2 = gw - QROWS - KROWS;
        int b = w2 / (NKV*TE); int r = w2 % (NKV*TE); int h = r / TE; int t = r % TE;
        const float* src = &g_qkv[((size_t)(b*TE)+t)*DIMM + 768 + h*DD];
        size_t doff = (((size_t)(b*NKV+h))*TE + t)*DD;
        g_vh[doff + lane]      = __float2half(src[lane]);
        g_vh[doff + lane + 32] = __float2half(src[lane+32]);
    }
}

// ================= HMMA flash attention, split-KV, 2-pass fp16 =================
// smem: Qh 0 | Ql 8K | Kh 16K | Vh 24K  (32KB)
__global__ void __launch_bounds__(128) attn_mma_kernel(const float* __restrict__ attn_scale)
{
    extern __shared__ char smc[];
    const uint32_t smb = smem_u32(smc);
    const int b = blockIdx.z, h = blockIdx.y;
    int qt, ci;
    chunk_map(ACH_PER_BH - 1 - (int)blockIdx.x, qt, ci);
    const int nch = (qt >> 3) + 1;
    const int q0 = qt << 6;
    const int kt_begin = ci << 3;
    const int kt_end = min(kt_begin + 8, qt + 1);
    const int hkv = h >> 1;
    const int tid = threadIdx.x, l = tid & 31, w = tid >> 5;

    const size_t qbase = ((size_t)(b*NATTN+h))*TE;
    const size_t kvbase = ((size_t)(b*NKV+hkv))*TE;

    auto loadK = [&](int k0) {
        for (int i = tid; i < 512; i += 128) {
            int row = i >> 3, seg = i & 7;
            uint32_t dst = smb + 16384 + row*128 + ((seg*16) ^ ((row & 7) << 4));
            int krow = k0 + row;
            int ok = krow < TE;
            cpasync16(dst, g_kh + (kvbase + (ok ? krow : 0))*DD + seg*8, ok ? 16 : 0);
        }
        CP_COMMIT();
    };
    auto loadV = [&](int k0) {
        for (int i = tid; i < 512; i += 128) {
            int row = i >> 3, seg = i & 7;
            uint32_t dst = smb + 24576 + row*128 + ((seg*16) ^ ((row & 7) << 4));
            int krow = k0 + row;
            int ok = krow < TE;
            cpasync16(dst, g_vh + (kvbase + (ok ? krow : 0))*DD + seg*8, ok ? 16 : 0);
        }
        CP_COMMIT();
    };

    {   // prologue: {Q, K(kt_begin)}, {V(kt_begin)}
        for (int i = tid; i < 1024; i += 128) {
            int tile = i >> 9, idx = i & 511, row = idx >> 3, seg = idx & 7;
            uint32_t dst = smb + tile*8192 + row*128 + ((seg*16) ^ ((row & 7) << 4));
            int qrow = q0 + row;
            int ok = qrow < TE;
            const __half* base = tile ? g_ql : g_qh;
            cpasync16(dst, base + (qbase + (ok ? qrow : 0))*DD + seg*8, ok ? 16 : 0);
        }
        for (int i = tid; i < 512; i += 128) {
            int row = i >> 3, seg = i & 7;
            uint32_t dst = smb + 16384 + row*128 + ((seg*16) ^ ((row & 7) << 4));
            int krow = (kt_begin << 6) + row;
            int ok = krow < TE;
            cpasync16(dst, g_kh + (kvbase + (ok ? krow : 0))*DD + seg*8, ok ? 16 : 0);
        }
        CP_COMMIT();
        loadV(kt_begin << 6);
    }

    float sO[8][4];
#pragma unroll
    for (int nf = 0; nf < 8; nf++)
#pragma unroll
        for (int q = 0; q < 4; q++) sO[nf][q] = 0.f;
    float m0r = -1e30f, m1r = -1e30f, l0r = 0.f, l1r = 0.f;

    const int grow0 = q0 + w*16 + (l >> 2);
    const int grow1 = grow0 + 8;

    for (int kt = kt_begin; kt < kt_end; kt++) {
        const int k0 = kt << 6;
        CP_WAIT1();
        __syncthreads();

        float s[8][4];
#pragma unroll
        for (int nf = 0; nf < 8; nf++)
#pragma unroll
            for (int q = 0; q < 4; q++) s[nf][q] = 0.f;

#pragma unroll
        for (int kc = 0; kc < 4; kc++) {
            uint32_t aH[4], aL[4], bk[8][2];
            {
                int row = w*16 + (l & 15);
                int kb = kc*32 + ((l >> 4) << 4);
                uint32_t ad = smb + row*128 + (kb ^ ((row & 7) << 4));
                ldsm4(aH, ad);
                ldsm4(aL, ad + 8192);
            }
#pragma unroll
            for (int nj = 0; nj < 4; nj++) {
                int row = nj*16 + (l & 7) + ((l >> 4) << 3);
                int kb = kc*32 + (((l >> 3) & 1) << 4);
                uint32_t bd = smb + 16384 + row*128 + (kb ^ ((row & 7) << 4));
                uint32_t t[4];
                ldsm4(t, bd);
                bk[nj*2][0]=t[0]; bk[nj*2][1]=t[1]; bk[nj*2+1][0]=t[2]; bk[nj*2+1][1]=t[3];
            }
#pragma unroll
            for (int nf = 0; nf < 8; nf++) {
                mma16816h(s[nf], aH, bk[nf]);
                mma16816h(s[nf], aL, bk[nf]);
            }
        }
        __syncthreads();
        if (kt + 1 < kt_end) loadK((kt + 1) << 6);

        const bool diag = (kt == qt);
#pragma unroll
        for (int nf = 0; nf < 8; nf++) {
            int c0 = k0 + nf*8 + ((l & 3) << 1);
            s[nf][0] *= 0.125f; s[nf][1] *= 0.125f;
            s[nf][2] *= 0.125f; s[nf][3] *= 0.125f;
            if (diag) {
                if (c0     > grow0) s[nf][0] = -1e30f;
                if (c0 + 1 > grow0) s[nf][1] = -1e30f;
                if (c0     > grow1) s[nf][2] = -1e30f;
                if (c0 + 1 > grow1) s[nf][3] = -1e30f;
            }
        }

        float mx0 = -1e30f, mx1 = -1e30f;
#pragma unroll
        for (int nf = 0; nf < 8; nf++) {
            mx0 = fmaxf(mx0, fmaxf(s[nf][0], s[nf][1]));
            mx1 = fmaxf(mx1, fmaxf(s[nf][2], s[nf][3]));
        }
        mx0 = fmaxf(mx0, __shfl_xor_sync(0xffffffffu, mx0, 1));
        mx0 = fmaxf(mx0, __shfl_xor_sync(0xffffffffu, mx0, 2));
        mx1 = fmaxf(mx1, __shfl_xor_sync(0xffffffffu, mx1, 1));
        mx1 = fmaxf(mx1, __shfl_xor_sync(0xffffffffu, mx1, 2));
        float mn0 = fmaxf(m0r, mx0), mn1 = fmaxf(m1r, mx1);
        float al0 = __expf(m0r - mn0), al1 = __expf(m1r - mn1);
        m0r = mn0; m1r = mn1;

        float rs0 = 0.f, rs1 = 0.f;
#pragma unroll
        for (int nf = 0; nf < 8; nf++) {
            float p0 = __expf(s[nf][0] - mn0), p1 = __expf(s[nf][1] - mn0);
            float p2 = __expf(s[nf][2] - mn1), p3 = __expf(s[nf][3] - mn1);
            rs0 += p0 + p1; rs1 += p2 + p3;
            s[nf][0] = p0; s[nf][1] = p1; s[nf][2] = p2; s[nf][3] = p3;
        }
        rs0 += __shfl_xor_sync(0xffffffffu, rs0, 1);
        rs0 += __shfl_xor_sync(0xffffffffu, rs0, 2);
        rs1 += __shfl_xor_sync(0xffffffffu, rs1, 1);
        rs1 += __shfl_xor_sync(0xffffffffu, rs1, 2);
        l0r = l0r*al0 + rs0;
        l1r = l1r*al1 + rs1;

#pragma unroll
        for (int nf = 0; nf < 8; nf++) {
            sO[nf][0] *= al0; sO[nf][1] *= al0;
            sO[nf][2] *= al1; sO[nf][3] *= al1;
        }

        if (kt + 1 < kt_end) { CP_WAIT1(); } else { CP_WAIT0(); }
        __syncthreads();

#pragma unroll
        for (int kc = 0; kc < 4; kc++) {
            uint32_t pH[4], pL[4], bv[8][2];
            hfsplit2(s[2*kc][0],   s[2*kc][1],   pH[0], pL[0]);
            hfsplit2(s[2*kc][2],   s[2*kc][3],   pH[1], pL[1]);
            hfsplit2(s[2*kc+1][0], s[2*kc+1][1], pH[2], pL[2]);
            hfsplit2(s[2*kc+1][2], s[2*kc+1][3], pH[3], pL[3]);
#pragma unroll
            for (int i2 = 0; i2 < 4; i2++) {
                int row = kc*16 + (l & 7) + (((l >> 3) & 1) << 3);
                int cb = i2*32 + (((l >> 4) & 1) << 4);
                uint32_t vd = smb + 24576 + row*128 + (cb ^ ((row & 7) << 4));
                uint32_t t[4];
                ldsm4t(t, vd);
                bv[2*i2][0]=t[0]; bv[2*i2][1]=t[1]; bv[2*i2+1][0]=t[2]; bv[2*i2+1][1]=t[3];
            }
#pragma unroll
            for (int nf = 0; nf < 8; nf++) {
                mma16816h(sO[nf], pH, bv[nf]);
                mma16816h(sO[nf], pL, bv[nf]);
            }
        }
        __syncthreads();
        if (kt + 1 < kt_end) loadV((kt + 1) << 6);
    }

    if (nch == 1) {
        float ascale = attn_scale[0];
        float inv0 = ascale / l0r, inv1 = ascale / l1r;
#pragma unroll
        for (int nf = 0; nf < 8; nf++) {
            int oc = h*DD + nf*8 + ((l & 3) << 1);
            if (grow0 >= NMETA && grow0 < TE) {
                uint32_t hi, lo; hfsplit2(sO[nf][0]*inv0, sO[nf][1]*inv0, hi, lo);
                size_t base = ((size_t)(b*TT) + (grow0 - NMETA))*DIMM + oc;
                *(uint32_t*)&g_cath[base] = hi;
                *(uint32_t*)&g_catl[base] = lo;
            }
            if (grow1 >= NMETA && grow1 < TE) {
                uint32_t hi, lo; hfsplit2(sO[nf][2]*inv1, sO[nf][3]*inv1, hi, lo);
                size_t base = ((size_t)(b*TT) + (grow1 - NMETA))*DIMM + oc;
                *(uint32_t*)&g_cath[base] = hi;
                *(uint32_t*)&g_catl[base] = lo;
            }
        }
    } else {
        const int slot = (((b*NATTN+h)*NQT) + qt)*5 + ci;
        float* po = g_pO + (size_t)slot*4096;
        const int r0 = w*16 + (l >> 2), r1 = r0 + 8;
#pragma unroll
        for (int nf = 0; nf < 8; nf++) {
            int ccol = nf*8 + ((l & 3) << 1);
            *(float2*)&po[r0*64 + ccol] = make_float2(sO[nf][0], sO[nf][1]);
            *(float2*)&po[r1*64 + ccol] = make_float2(sO[nf][2], sO[nf][3]);
        }
        if ((l & 3) == 0) {
            g_pml[(size_t)slot*64 + r0] = make_float2(m0r, l0r);
            g_pml[(size_t)slot*64 + r1] = make_float2(m1r, l1r);
        }
    }
}

// ================= attention merge (qt >= 8) =================
__global__ void __launch_bounds__(256) attn_merge_kernel(const float* __restrict__ attn_scale)
{
    const int b = blockIdx.z, h = blockIdx.y;
    const int qt = 8 + (int)blockIdx.x;
    const int nch = (qt >> 3) + 1;
    const int tid = threadIdx.x;
    const int r = tid >> 2, cg = (tid & 3) << 4;
    const int slot0 = (((b*NATTN+h)*NQT) + qt)*5;

    float mi[5], li[5];
    float mstar = -1e30f;
    for (int ci = 0; ci < nch; ci++) {
        float2 ml = g_pml[(size_t)(slot0+ci)*64 + r];
        mi[ci] = ml.x; li[ci] = ml.y;
        mstar = fmaxf(mstar, ml.x);
    }
    float L = 0.f;
    float wf[5];
    for (int ci = 0; ci < nch; ci++) {
        wf[ci] = __expf(mi[ci] - mstar);
        L += wf[ci]*li[ci];
    }
    float acc[16];
#pragma unroll
    for (int j = 0; j < 16; j++) acc[j] = 0.f;
    for (int ci = 0; ci < nch; ci++) {
        const float* po = g_pO + (size_t)(slot0+ci)*4096 + r*64 + cg;
        float wfc = wf[ci];
#pragma unroll
        for (int j = 0; j < 16; j += 4) {
            float4 v = *(const float4*)&po[j];
            acc[j]   += wfc*v.x; acc[j+1] += wfc*v.y;
            acc[j+2] += wfc*v.z; acc[j+3] += wfc*v.w;
        }
    }
    int q = (qt << 6) + r;
    if (q >= NMETA && q < TE) {
        float sc = attn_scale[0] / L;
        size_t base = ((size_t)(b*TT) + (q - NMETA))*DIMM + h*DD + cg;
#pragma unroll
        for (int j = 0; j < 16; j += 2) {
            uint32_t hi, lo;
            hfsplit2(acc[j]*sc, acc[j+1]*sc, hi, lo);
            *(uint32_t*)&g_cath[base + j] = hi;
            *(uint32_t*)&g_catl[base + j] = lo;
        }
    }
}

// ================= SSM: dt / a / Bx / Cc =================
__global__ void dtbc_kernel(const float* __restrict__ dtw, const float* __restrict__ dtb,
                            const float* __restrict__ Bw,  const float* __restrict__ Cw,
                            const float* __restrict__ logA)
{
    __shared__ float xs[64][65];
    __shared__ float ws[48][65];
    __shared__ float dts[64][16];
    const int b = blockIdx.z, h = blockIdx.y, t0 = blockIdx.x*64;
    const int tid = threadIdx.x;

    for (int idx = tid; idx < 48*64; idx += 256) {
        int o = idx >> 6, k = idx & 63;
        float v;
        if (o < 16)      v = dtw[(h*16+o)*64 + k];
        else if (o < 32) v = Bw[(h*16+(o-16))*64 + k];
        else             v = Cw[(h*16+(o-32))*64 + k];
        ws[o][k] = v;
    }
    for (int idx = tid; idx < 64*64; idx += 256) {
        int r = idx >> 6, k = idx & 63;
        xs[r][k] = g_ssmx[((size_t)(b*TT)+t0+r)*(NSSM*DD) + h*DD + k];
    }
    __syncthreads();

    const int r = tid >> 2;
    const size_t obase = (((size_t)(b*NSSM+h))*TT + t0 + r)*SS;

    {
        int so = (tid & 3) << 2;
#pragma unroll
        for (int q = 0; q < 4; q++) {
            int o = so + q;
            float d = 0.f;
#pragma unroll
            for (int k = 0; k < 64; k++) d += xs[r][k]*ws[o][k];
            d += dtb[h*16 + o];
            float sp = (d > 20.f) ? d : log1pf(expf(d));
            float dt = fminf(sp, 1.0f);
            dts[r][o] = dt;
            float A  = fminf(-expf(logA[h*16 + o]), 10.0f);
            float la = fminf(fmaxf(dt*A, -0.5f), 0.0f);
            g_au[obase + o].x = expf(la);
        }
    }
    __syncthreads();
    {
        int jo = (tid & 3) << 3;
#pragma unroll
        for (int q = 0; q < 8; q++) {
            int o2 = jo + q;
            float d = 0.f;
#pragma unroll
            for (int k = 0; k < 64; k++) d += xs[r][k]*ws[16+o2][k];
            if (o2 < 16) g_au[obase + o2].y     = d * dts[r][o2];
            else         g_cc[obase + (o2-16)]  = d;
        }
    }
}

// ================= scan phase 1 =================
__global__ void scan1_kernel()
{
    const int bh = blockIdx.x >> 2, cg = blockIdx.x & 3;
    const int s = threadIdx.x & 15, ckl = threadIdx.x >> 4;
    const int chunk = cg*16 + ckl;
    const int t0 = chunk*SC_L;
    const size_t base = (size_t)bh*TT*SS + s;

    float hv = 0.f, p = 1.f;
#pragma unroll 4
    for (int t = 0; t < SC_L; t++) {
        size_t o = base + (size_t)(t0 + t)*SS;
        float2 au = g_au[o];
        p *= au.x;
        hv = fmaf(au.x, hv, au.y);
        g_hbuf[o] = hv;
        g_pp[o] = p;
    }
    g_carry[(bh*SS + s)*SC_C + chunk] = make_float2(hv, p);
}

// ================= scan phase 2 =================
__global__ void scan2_kernel()
{
    int lane = blockIdx.x*64 + threadIdx.x;
    if (lane >= BB*NSSM*SS) return;
    float hin = 0.f;
    const int cb = lane*SC_C;
#pragma unroll 4
    for (int c = 0; c < SC_C; c++) {
        g_hin[cb + c] = hin;
        float2 cr = g_carry[cb + c];
        hin = fmaf(cr.y, hin, cr.x);
    }
}

// ================= SSM epilogue =================
__global__ void ssmout_kernel(const float* __restrict__ Ow, const float* __restrict__ ssm_scale)
{
    __shared__ float hs[64][17];
    __shared__ float cs[64][17];
    __shared__ float ows[64][17];
    const int b = blockIdx.z, h = blockIdx.y, t0 = blockIdx.x*64;
    const int tid = threadIdx.x;
    const int bh = b*NSSM + h;

    for (int idx = tid; idx < 64*16; idx += 256) {
        int r = idx >> 4, s = idx & 15;
        int t = t0 + r;
        size_t src = ((size_t)bh*TT + t)*SS + s;
        float hin = g_hin[(bh*SS + s)*SC_C + (t >> 5)];
        hs[r][s] = fmaf(g_pp[src], hin, g_hbuf[src]);
        cs[r][s] = g_cc[src];
        ows[r][s] = Ow[(h*64 + r)*16 + s];
    }
    __syncthreads();

    const int r = tid >> 2, dp = tid & 3;
    float y = 0.f;
#pragma unroll
    for (int s = 0; s < 16; s++) y += cs[r][s]*hs[r][s];
    float x0 = g_ssmx[((size_t)(b*TT)+t0+r)*(NSSM*DD) + h*DD];
    float sc = ssm_scale[0];
    float yx = y * x0;
    size_t ob = ((size_t)(b*TT)+t0+r)*DIMM + 512 + h*DD + dp*16;
#pragma unroll
    for (int q = 0; q < 16; q += 2) {
        int d = dp*16 + q;
        float v0 = yx, v1 = yx;
#pragma unroll
        for (int s = 0; s < 16; s++) {
            v0 += hs[r][s]*ows[d][s];
            v1 += hs[r][s]*ows[d+1][s];
        }
        v0 *= sc; v1 *= sc;
        uint32_t hi, lo;
        hfsplit2(v0, v1, hi, lo);
        *(uint32_t*)&g_cath[ob + q] = hi;
        *(uint32_t*)&g_catl[ob + q] = lo;
    }
}

// ================= launch =================
extern "C" void kernel_launch(void* const* d_in, const int* in_sizes, int n_in,
                              void* d_out, int out_size)
{
    const float* x         = (const float*)d_in[0];
    const float* meta      = (const float*)d_in[1];
    const float* qw        = (const float*)d_in[2];
    const float* kw        = (const float*)d_in[3];
    const float* vw        = (const float*)d_in[4];
    const float* qgain     = (const float*)d_in[5];
    const float* ssm_in_w  = (const float*)d_in[6];
    const float* projw     = (const float*)d_in[7];
    const float* attn_sc   = (const float*)d_in[8];
    const float* ssm_sc    = (const float*)d_in[9];
    const float* logA      = (const float*)d_in[10];
    const float* Bw        = (const float*)d_in[11];
    const float* Cw        = (const float*)d_in[12];
    const float* dtw       = (const float*)d_in[13];
    const float* dtb       = (const float*)d_in[14];
    const float* Ow        = (const float*)d_in[15];
    float* out = (float*)d_out;

    __half *p_xh, *p_xl, *p_wqh, *p_wsh, *p_wph, *p_cth, *p_ctl;
    float *p_qkv, *p_ssmx;
    cudaGetSymbolAddress((void**)&p_xh,  g_xh);
    cudaGetSymbolAddress((void**)&p_xl,  g_xl);
    cudaGetSymbolAddress((void**)&p_wqh, g_wqkvh);
    cudaGetSymbolAddress((void**)&p_wsh, g_wsh);
    cudaGetSymbolAddress((void**)&p_wph, g_wph);
    cudaGetSymbolAddress((void**)&p_cth, g_cath);
    cudaGetSymbolAddress((void**)&p_ctl, g_catl);
    cudaGetSymbolAddress((void**)&p_qkv,  g_qkv);
    cudaGetSymbolAddress((void**)&p_ssmx, g_ssmx);

    const int GEMM_SMEM = 2*49152;
    cudaFuncSetAttribute(gemm_mma_kernel, cudaFuncAttributeMaxDynamicSharedMemorySize, GEMM_SMEM);
    const int ATTN_SMEM = 4*8192;                                 // 32768
    cudaFuncSetAttribute(attn_mma_kernel, cudaFuncAttributeMaxDynamicSharedMemorySize, ATTN_SMEM);

    const int CV_TOTAL = CV_XN + CV_W1 + CV_W2 + CV_W3;

    conv_all_kernel<<<(CV_TOTAL + 255)/256, 256>>>(x, meta, qw, kw, vw, ssm_in_w, projw);
    gemm_mma_kernel<<<dim3(DIMM/128, (BB*TE + 127)/128), 256, GEMM_SMEM>>>(
        p_xh, p_xl, p_wqh, p_qkv, BB*TE, DIMM, 0);
    {
        int warps = BB*(NATTN + NKV + NKV)*TE;
        normrot_kernel<<<(warps*32 + 255)/256, 256>>>(qgain);
    }
    attn_mma_kernel<<<dim3(ACH_PER_BH, NATTN, BB), 128, ATTN_SMEM>>>(attn_sc);
    attn_merge_kernel<<<dim3(NQT - 8, NATTN, BB), 256>>>(attn_sc);
    gemm_mma_kernel<<<dim3((NSSM*DD)/128, (BB*TT)/128), 256, GEMM_SMEM>>>(
        p_xh, p_xl, p_wsh, p_ssmx, BB*TT, NSSM*DD, 1);
    dtbc_kernel<<<dim3(TT/64, NSSM, BB), 256>>>(dtw, dtb, Bw, Cw, logA);
    scan1_kernel<<<64, 256>>>();
    scan2_kernel<<<4, 64>>>();
    ssmout_kernel<<<dim3(TT/64, NSSM, BB), 256>>>(Ow, ssm_sc);
    gemm_mma_kernel<<<dim3(DIMM/128, (BB*TT)/128), 256, GEMM_SMEM>>>(
        p_cth, p_ctl, p_wph, out, BB*TT, DIMM, 0);
}